// round 9
// baseline (speedup 1.0000x reference)
#include <cuda_runtime.h>
#include <cuda_bf16.h>
#include <cstdint>

typedef unsigned long long ull;
typedef unsigned int uint;

// ================= helpers =================
__device__ __forceinline__ void ffma2(ull& d, ull a, ull b) {
    asm("fma.rn.f32x2 %0, %1, %2, %0;" : "+l"(d) : "l"(a), "l"(b));
}
__device__ __forceinline__ ull pack2(float x, float y) {
    ull d; asm("mov.b64 %0, {%1, %2};" : "=l"(d) : "f"(x), "f"(y)); return d;
}
__device__ __forceinline__ float fast_sigmoid(float x) {
    float t;
    asm("tanh.approx.f32 %0, %1;" : "=f"(t) : "f"(x * 0.5f));
    return fmaf(t, 0.5f, 0.5f);
}
__device__ __forceinline__ uint bfpack(float x, float y) {
    __nv_bfloat16 bx = __float2bfloat16(x), by = __float2bfloat16(y);
    return (uint)__bfloat16_as_ushort(bx) | ((uint)__bfloat16_as_ushort(by) << 16);
}
__device__ __forceinline__ void split2(float x, float y, uint& hi, uint& lo) {
    __nv_bfloat16 hx = __float2bfloat16(x), hy = __float2bfloat16(y);
    hi = (uint)__bfloat16_as_ushort(hx) | ((uint)__bfloat16_as_ushort(hy) << 16);
    lo = bfpack(x - __bfloat162float(hx), y - __bfloat162float(hy));
}
__device__ __forceinline__ void mma_bf16(float* d, const uint* a, uint b0, uint b1) {
    asm volatile(
        "mma.sync.aligned.m16n8k16.row.col.f32.bf16.bf16.f32 "
        "{%0,%1,%2,%3}, {%4,%5,%6,%7}, {%8,%9}, {%0,%1,%2,%3};"
        : "+f"(d[0]), "+f"(d[1]), "+f"(d[2]), "+f"(d[3])
        : "r"(a[0]), "r"(a[1]), "r"(a[2]), "r"(a[3]), "r"(b0), "r"(b1));
}
__device__ __forceinline__ uint smem_u32(const void* p) {
    uint a;
    asm("{ .reg .u64 t; cvta.to.shared.u64 t, %1; cvt.u32.u64 %0, t; }" : "=r"(a) : "l"(p));
    return a;
}
__device__ __forceinline__ void cp_async16(uint saddr, const void* gptr) {
    asm volatile("cp.async.cg.shared.global [%0], [%1], 16;" :: "r"(saddr), "l"(gptr));
}
#define CP_COMMIT() asm volatile("cp.async.commit_group;" ::: "memory")
#define CP_WAIT0()  asm volatile("cp.async.wait_group 0;" ::: "memory")

// ================= constants =================
#define RDIM 384
#define SDIM 2048
#define CE   64
#define HC   64
#define QSCALE 0.35355339059327373f
#define NCH  8
#define CHUNK 256

// ================= scratch =================
__device__ float g_o[RDIM * HC];
__device__ float g_kv[(size_t)RDIM * SDIM * 16];
__device__ float g_poolq[RDIM * 64 * 64];
__device__ float g_poold[RDIM * 64];
__device__ float g_qproj[RDIM * 64];
__device__ float g_ov[RDIM * NCH * 64];
__device__ float g_mx[RDIM * NCH * 8];
__device__ float g_sm[RDIM * NCH * 8];

// ============================================================================
// K1: persistent pipelined kv projection + pooling partials. (unchanged)
// ============================================================================
#define KV_GRID 304
#define KV_NT   (RDIM * (SDIM / 128))
#define BUFW    68
#define ASTW    36
#define KV_BUF_FLOATS (128 * BUFW)
#define KV_W_OFF (2 * KV_BUF_FLOATS)
#define KV_SMEM_FLOATS (KV_W_OFF + 2 * 16 * ASTW)
#define KV_SMEM_BYTES  (KV_SMEM_FLOATS * 4)

__global__ void __launch_bounds__(128, 2)
kv_kernel(const float* __restrict__ m, const float* __restrict__ mask,
          const float* __restrict__ Wk, const float* __restrict__ Wv) {
    extern __shared__ __align__(16) float skf[];
    float* bufs[2] = { skf, skf + KV_BUF_FLOATS };
    uint* wkv_hi = (uint*)(skf + KV_W_OFF);
    uint* wkv_lo = wkv_hi + 16 * ASTW;

    const int tid  = threadIdx.x;
    const int lane = tid & 31;
    const int warp = tid >> 5;
    const int g    = lane >> 2;
    const int tg   = lane & 3;
    const int rowbase = warp * 32;

    const uint buf_u32[2] = { smem_u32(bufs[0]), smem_u32(bufs[1]) };

    for (int i = tid; i < 512; i += 128) {
        const int row = i >> 5, kp = i & 31;
        const float* W = (row < 8) ? (Wk + row * 64) : (Wv + (row - 8) * 64);
        float2 w = *(const float2*)(W + kp * 2);
        uint hi, lo; split2(w.x, w.y, hi, lo);
        wkv_hi[row * ASTW + kp] = hi;
        wkv_lo[row * ASTW + kp] = lo;
    }

    int t0 = blockIdx.x;
    {
        const int r = t0 >> 4, sbase = (t0 & 15) * 128;
#pragma unroll
        for (int i = 0; i < 16; i++) {
            const int idx = tid + 128 * i;
            const int row = idx >> 4;
            const int c4  = (idx & 15) * 4;
            cp_async16(buf_u32[0] + (uint)(row * BUFW + c4) * 4,
                       m + ((size_t)r * SDIM + sbase + row) * CE + c4);
        }
        CP_COMMIT();
    }

    int cur = 0;
#pragma unroll 1
    for (int t = t0; t < KV_NT; t += KV_GRID, cur ^= 1) {
        const int r     = t >> 4;
        const int ts    = t & 15;
        const int sbase = ts * 128;

        CP_WAIT0();
        __syncthreads();

        const int tn = t + KV_GRID;
        if (tn < KV_NT) {
            const int rn = tn >> 4, sbn = (tn & 15) * 128;
#pragma unroll
            for (int i = 0; i < 16; i++) {
                const int idx = tid + 128 * i;
                const int row = idx >> 4;
                const int c4  = (idx & 15) * 4;
                cp_async16(buf_u32[cur ^ 1] + (uint)(row * BUFW + c4) * 4,
                           m + ((size_t)rn * SDIM + sbn + row) * CE + c4);
            }
            CP_COMMIT();
        }

        const float* buf = bufs[cur];

        {
            const float mskv = mask[(size_t)r * SDIM + sbase + rowbase + lane];
            ull qn = 0ull;
            float qden = 0.0f;
#pragma unroll 8
            for (int i = 0; i < 32; i++) {
                const float msk = __shfl_sync(0xffffffffu, mskv, i);
                const ull mv = *(const ull*)&buf[(rowbase + i) * BUFW + 2 * lane];
                ffma2(qn, mv, pack2(msk, msk));
                qden += msk;
            }
            const int p = (r * 16 + ts) * 4 + warp;
            *(ull*)&g_poolq[(size_t)p * 64 + 2 * lane] = qn;
            if (lane == 0) g_poold[p] = qden;
        }

        float d[2][2][4];
#pragma unroll
        for (int mt = 0; mt < 2; mt++)
#pragma unroll
            for (int nt = 0; nt < 2; nt++)
#pragma unroll
                for (int q = 0; q < 4; q++) d[mt][nt][q] = 0.0f;

#pragma unroll
        for (int kt = 0; kt < 4; kt++) {
            uint ah[2][4], al[2][4];
#pragma unroll
            for (int mt = 0; mt < 2; mt++) {
                const int r0 = rowbase + mt * 16 + g;
                const float2 f0 = *(const float2*)&buf[r0 * BUFW + 16 * kt + 2 * tg];
                const float2 f1 = *(const float2*)&buf[(r0 + 8) * BUFW + 16 * kt + 2 * tg];
                const float2 f2 = *(const float2*)&buf[r0 * BUFW + 16 * kt + 2 * tg + 8];
                const float2 f3 = *(const float2*)&buf[(r0 + 8) * BUFW + 16 * kt + 2 * tg + 8];
                split2(f0.x, f0.y, ah[mt][0], al[mt][0]);
                split2(f1.x, f1.y, ah[mt][1], al[mt][1]);
                split2(f2.x, f2.y, ah[mt][2], al[mt][2]);
                split2(f3.x, f3.y, ah[mt][3], al[mt][3]);
            }
#pragma unroll
            for (int p = 0; p < 3; p++) {
                const uint* wb = (p == 1) ? wkv_lo : wkv_hi;
                const uint (*af)[4] = (p == 2) ? al : ah;
#pragma unroll
                for (int nt = 0; nt < 2; nt++) {
                    const uint b0 = wb[(nt * 8 + g) * ASTW + kt * 8 + tg];
                    const uint b1 = wb[(nt * 8 + g) * ASTW + kt * 8 + tg + 4];
                    mma_bf16(d[0][nt], af[0], b0, b1);
                    mma_bf16(d[1][nt], af[1], b0, b1);
                }
            }
        }

#pragma unroll
        for (int mt = 0; mt < 2; mt++) {
#pragma unroll
            for (int nt = 0; nt < 2; nt++) {
                const int c0 = nt * 8 + 2 * tg;
                const int r0 = rowbase + mt * 16 + g;
                *(float2*)&g_kv[((size_t)r * SDIM + sbase + r0) * 16 + c0] =
                    make_float2(d[mt][nt][0], d[mt][nt][1]);
                *(float2*)&g_kv[((size_t)r * SDIM + sbase + r0 + 8) * 16 + c0] =
                    make_float2(d[mt][nt][2], d[mt][nt][3]);
            }
        }
    }
}

// ============================================================================
// K2: reduce pooling partials -> q -> qproj. (unchanged)
// ============================================================================
__global__ void __launch_bounds__(64, 8)
qk2_kernel(const float* __restrict__ Wq) {
    __shared__ float qpool[64];
    const int r   = blockIdx.x;
    const int tid = threadIdx.x;

    float qs = 0.0f, qd = 0.0f;
#pragma unroll 8
    for (int p = 0; p < 64; p++) {
        qs += g_poolq[(size_t)(r * 64 + p) * 64 + tid];
        qd += g_poold[r * 64 + p];
    }
    qpool[tid] = qs / (qd + 1e-10f);
    __syncthreads();

    float acc = 0.0f;
    const float* wqr = Wq + tid * 64;
#pragma unroll
    for (int e = 0; e < 64; e++) acc = fmaf(qpool[e], wqr[e], acc);
    g_qproj[r * 64 + tid] = acc * QSCALE;
}

// ============================================================================
// K3: logits + chunk softmax partials + partial o. (unchanged)
// ============================================================================
__global__ void __launch_bounds__(256, 3)
attn3_kernel(const float* __restrict__ mask) {
    __shared__ float v_sh[256 * 9];
    __shared__ float a_sh[256 * 8];
    __shared__ float qp_sh[64];
    __shared__ float wred[64];
    __shared__ float mx_sh[8];

    const int tid  = threadIdx.x;
    const int lane = tid & 31;
    const int warp = tid >> 5;
    const int ch   = blockIdx.x;
    const int r    = blockIdx.y;
    const int sbase = ch * CHUNK;

    if (tid < 64) qp_sh[tid] = g_qproj[r * 64 + tid];

    const float* kvrow = &g_kv[((size_t)r * SDIM + sbase + tid) * 16];
    const float4 k01 = *(const float4*)(kvrow);
    const float4 k23 = *(const float4*)(kvrow + 4);
    const float4 v01 = *(const float4*)(kvrow + 8);
    const float4 v23 = *(const float4*)(kvrow + 12);
    float kreg[8] = { k01.x, k01.y, k01.z, k01.w, k23.x, k23.y, k23.z, k23.w };
    v_sh[tid * 9 + 0] = v01.x; v_sh[tid * 9 + 1] = v01.y;
    v_sh[tid * 9 + 2] = v01.z; v_sh[tid * 9 + 3] = v01.w;
    v_sh[tid * 9 + 4] = v23.x; v_sh[tid * 9 + 5] = v23.y;
    v_sh[tid * 9 + 6] = v23.z; v_sh[tid * 9 + 7] = v23.w;

    const float mymsk = mask[(size_t)r * SDIM + sbase + tid];
    __syncthreads();

    float lg[8];
    const float bias = (mymsk - 1.0f) * 1e9f;
#pragma unroll
    for (int h = 0; h < 8; h++) {
        float v = bias;
#pragma unroll
        for (int c = 0; c < 8; c++) v = fmaf(qp_sh[h * 8 + c], kreg[c], v);
        lg[h] = v;
    }

    float wm[8];
#pragma unroll
    for (int h = 0; h < 8; h++) {
        float v = lg[h];
#pragma unroll
        for (int off = 16; off > 0; off >>= 1)
            v = fmaxf(v, __shfl_xor_sync(0xffffffffu, v, off));
        wm[h] = v;
    }
    if (lane == 0)
#pragma unroll
        for (int h = 0; h < 8; h++) wred[warp * 8 + h] = wm[h];
    __syncthreads();
    if (tid < 8) {
        float v = -1e30f;
#pragma unroll
        for (int w = 0; w < 8; w++) v = fmaxf(v, wred[w * 8 + tid]);
        mx_sh[tid] = v;
    }
    __syncthreads();

    float sm[8];
#pragma unroll
    for (int h = 0; h < 8; h++) {
        const float e = __expf(lg[h] - mx_sh[h]);
        a_sh[tid * 8 + h] = e;
        float v = e;
#pragma unroll
        for (int off = 16; off > 0; off >>= 1)
            v += __shfl_xor_sync(0xffffffffu, v, off);
        sm[h] = v;
    }
    __syncthreads();
    if (lane == 0)
#pragma unroll
        for (int h = 0; h < 8; h++) wred[warp * 8 + h] = sm[h];
    __syncthreads();
    if (tid < 8) {
        float v = 0.0f;
#pragma unroll
        for (int w = 0; w < 8; w++) v += wred[w * 8 + tid];
        g_sm[(r * NCH + ch) * 8 + tid] = v;
        g_mx[(r * NCH + ch) * 8 + tid] = mx_sh[tid];
    }

    {
        const int h = warp;
        const int c = lane & 7;
        const int sgrp = lane >> 3;
        float acc = 0.0f;
#pragma unroll 8
        for (int i = 0; i < 64; i++) {
            const int row = 4 * i + sgrp;
            acc = fmaf(a_sh[row * 8 + h], v_sh[row * 9 + c], acc);
        }
        acc += __shfl_xor_sync(0xffffffffu, acc, 8);
        acc += __shfl_xor_sync(0xffffffffu, acc, 16);
        if (lane < 8)
            g_ov[(r * NCH + ch) * 64 + h * 8 + c] = acc;
    }
}

// ============================================================================
// C': combine chunks -> g_o. (unchanged)
// ============================================================================
__global__ void __launch_bounds__(64, 8)
combine2_kernel() {
    __shared__ float wgt[8][8];
    __shared__ float den[8];

    const int r   = blockIdx.x;
    const int tid = threadIdx.x;

    if (tid < 8) {
        const int h = tid;
        float mxg = -1e30f;
#pragma unroll
        for (int c = 0; c < NCH; c++) mxg = fmaxf(mxg, g_mx[(r * NCH + c) * 8 + h]);
        float d = 0.0f;
#pragma unroll
        for (int c = 0; c < NCH; c++) {
            const float w = __expf(g_mx[(r * NCH + c) * 8 + h] - mxg);
            wgt[h][c] = w;
            d = fmaf(g_sm[(r * NCH + c) * 8 + h], w, d);
        }
        den[h] = d;
    }
    __syncthreads();

    const int h = tid >> 3;
    float acc = 0.0f;
#pragma unroll
    for (int c = 0; c < NCH; c++)
        acc = fmaf(g_ov[(r * NCH + c) * 64 + tid], wgt[h][c], acc);
    g_o[r * HC + tid] = acc / den[h];
}

// ============================================================================
// Gate v3 (persistent, fully-async loads): 256 threads, 8 warps, warp = 16
// rows. m AND add_to double-buffered via cp.async; t in registers.
// ============================================================================
#define G_GRID 152
#define G_NT   (RDIM * (SDIM / 128))
#define G_BUF_FLOATS (128 * BUFW)          // one m or add_to buffer
#define G_AB_OFF  (2 * G_BUF_FLOATS)       // add_to buffers after m buffers
#define G_W_OFF   (4 * G_BUF_FLOATS)
#define G_SMEM_FLOATS (G_W_OFF + 4 * 64 * ASTW + 128)
#define G_SMEM_BYTES  (G_SMEM_FLOATS * 4)

__global__ void __launch_bounds__(256, 1)
gate_kernel(const float* __restrict__ m, const float* __restrict__ Wg,
            const float* __restrict__ bg, const float* __restrict__ Wo,
            const float* __restrict__ bo, const float* __restrict__ add_to,
            float* __restrict__ out) {
    extern __shared__ __align__(16) float sgf[];
    float* mbuf[2] = { sgf, sgf + G_BUF_FLOATS };
    float* abuf[2] = { sgf + G_AB_OFF, sgf + G_AB_OFF + G_BUF_FLOATS };
    uint* wg_hi = (uint*)(sgf + G_W_OFF);
    uint* wg_lo = wg_hi + 64 * ASTW;
    uint* wo_hi = wg_lo + 64 * ASTW;
    uint* wo_lo = wo_hi + 64 * ASTW;
    float* bg_sh = (float*)(wo_lo + 64 * ASTW);
    float* bo_sh = bg_sh + 64;

    const int tid  = threadIdx.x;
    const int lane = tid & 31;
    const int warp = tid >> 5;
    const int g    = lane >> 2;
    const int tg   = lane & 3;
    const int rowbase = warp * 16;     // warp owns 16 rows

    const uint mbuf_u32[2] = { smem_u32(mbuf[0]), smem_u32(mbuf[1]) };
    const uint abuf_u32[2] = { smem_u32(abuf[0]), smem_u32(abuf[1]) };

    // ---- stage weights + biases ONCE ----
    for (int i = tid; i < 2048; i += 256) {
        const int row = i >> 5, kp = i & 31;
        {
            float2 w = *(const float2*)(Wg + row * 64 + kp * 2);
            uint hi, lo; split2(w.x, w.y, hi, lo);
            wg_hi[row * ASTW + kp] = hi;
            wg_lo[row * ASTW + kp] = lo;
        }
        {
            float2 w = *(const float2*)(Wo + row * 64 + kp * 2);
            uint hi, lo; split2(w.x, w.y, hi, lo);
            wo_hi[row * ASTW + kp] = hi;
            wo_lo[row * ASTW + kp] = lo;
        }
    }
    if (tid < 64) {
        bg_sh[tid] = bg[tid];
        bo_sh[tid] = bo[tid];
    }

    // ---- prefetch helper: m tile + add_to tile into stage st ----
    auto prefetch = [&](int t, int st) {
        const int r = t >> 4, sbase = (t & 15) * 128;
#pragma unroll
        for (int i = 0; i < 8; i++) {
            const int idx = tid + 256 * i;
            const int row = idx >> 4;
            const int c4  = (idx & 15) * 4;
            cp_async16(mbuf_u32[st] + (uint)(row * BUFW + c4) * 4,
                       m + ((size_t)r * SDIM + sbase + row) * CE + c4);
        }
#pragma unroll
        for (int i = 0; i < 8; i++) {
            const int idx = tid + 256 * i;
            const int row = idx >> 4;
            const int c4  = (idx & 15) * 4;
            cp_async16(abuf_u32[st] + (uint)(row * BUFW + c4) * 4,
                       add_to + ((size_t)(sbase + row) * RDIM + r) * CE + c4);
        }
        CP_COMMIT();
    };

    const int t0 = blockIdx.x;
    if (t0 < G_NT) prefetch(t0, 0);

    int cur = 0;
#pragma unroll 1
    for (int t = t0; t < G_NT; t += G_GRID, cur ^= 1) {
        const int r     = t >> 4;
        const int sbase = (t & 15) * 128;

        CP_WAIT0();
        __syncthreads();

        const int tn = t + G_GRID;
        if (tn < G_NT) prefetch(tn, cur ^ 1);

        const float* buf = mbuf[cur];
        float d[8][4];

        // ===== GEMM1: gate logits = m @ Wg^T =====
#pragma unroll
        for (int nt = 0; nt < 8; nt++)
#pragma unroll
            for (int q = 0; q < 4; q++) d[nt][q] = 0.0f;

#pragma unroll
        for (int kt = 0; kt < 4; kt++) {
            uint ah[4], al[4];
            {
                const int r0 = rowbase + g;
                const float2 f0 = *(const float2*)&buf[r0 * BUFW + 16 * kt + 2 * tg];
                const float2 f1 = *(const float2*)&buf[(r0 + 8) * BUFW + 16 * kt + 2 * tg];
                const float2 f2 = *(const float2*)&buf[r0 * BUFW + 16 * kt + 2 * tg + 8];
                const float2 f3 = *(const float2*)&buf[(r0 + 8) * BUFW + 16 * kt + 2 * tg + 8];
                split2(f0.x, f0.y, ah[0], al[0]);
                split2(f1.x, f1.y, ah[1], al[1]);
                split2(f2.x, f2.y, ah[2], al[2]);
                split2(f3.x, f3.y, ah[3], al[3]);
            }
#pragma unroll
            for (int p = 0; p < 3; p++) {
                const uint* wb = (p == 1) ? wg_lo : wg_hi;
                const uint* af = (p == 2) ? al : ah;
#pragma unroll
                for (int nt = 0; nt < 8; nt++) {
                    const uint b0 = wb[(nt * 8 + g) * ASTW + kt * 8 + tg];
                    const uint b1 = wb[(nt * 8 + g) * ASTW + kt * 8 + tg + 4];
                    mma_bf16(d[nt], af, b0, b1);
                }
            }
        }

        // ===== epilogue 1 (registers): t = sigmoid(d+bg)*o =====
        uint th[8][2], tl[8][2];
#pragma unroll
        for (int nt = 0; nt < 8; nt++) {
            const int c0 = nt * 8 + tg * 2;
            const float ov0 = __ldg(&g_o[r * HC + c0]);
            const float ov1 = __ldg(&g_o[r * HC + c0 + 1]);
            const float bg0 = bg_sh[c0], bg1 = bg_sh[c0 + 1];
            const float t0v = fast_sigmoid(d[nt][0] + bg0) * ov0;
            const float t1v = fast_sigmoid(d[nt][1] + bg1) * ov1;
            const float t2v = fast_sigmoid(d[nt][2] + bg0) * ov0;
            const float t3v = fast_sigmoid(d[nt][3] + bg1) * ov1;
            split2(t0v, t1v, th[nt][0], tl[nt][0]);
            split2(t2v, t3v, th[nt][1], tl[nt][1]);
        }

        // ===== GEMM2: out = t @ Wo^T =====
#pragma unroll
        for (int nt = 0; nt < 8; nt++)
#pragma unroll
            for (int q = 0; q < 4; q++) d[nt][q] = 0.0f;

#pragma unroll
        for (int p = 0; p < 3; p++) {
            const uint* wb = (p == 1) ? wo_lo : wo_hi;
#pragma unroll
            for (int kt = 0; kt < 4; kt++) {
                uint a[4];
                if (p == 2) {
                    a[0] = tl[2 * kt][0]; a[1] = tl[2 * kt][1];
                    a[2] = tl[2 * kt + 1][0]; a[3] = tl[2 * kt + 1][1];
                } else {
                    a[0] = th[2 * kt][0]; a[1] = th[2 * kt][1];
                    a[2] = th[2 * kt + 1][0]; a[3] = th[2 * kt + 1][1];
                }
#pragma unroll
                for (int nt = 0; nt < 8; nt++) {
                    const uint b0 = wb[(nt * 8 + g) * ASTW + kt * 8 + tg];
                    const uint b1 = wb[(nt * 8 + g) * ASTW + kt * 8 + tg + 4];
                    mma_bf16(d[nt], a, b0, b1);
                }
            }
        }

        // ===== epilogue 2: out = D + bo + add_to(smem) =====
        const float* ab = abuf[cur];
#pragma unroll
        for (int nt = 0; nt < 8; nt++) {
            const int c0 = nt * 8 + tg * 2;
            const float bo0 = bo_sh[c0], bo1 = bo_sh[c0 + 1];
            const int r0 = rowbase + g;
            {
                const float2 av = *(const float2*)&ab[r0 * BUFW + c0];
                const size_t base = ((size_t)(sbase + r0) * RDIM + r) * CE + c0;
                float2 ov;
                ov.x = d[nt][0] + bo0 + av.x;
                ov.y = d[nt][1] + bo1 + av.y;
                *(float2*)(out + base) = ov;
            }
            {
                const float2 av = *(const float2*)&ab[(r0 + 8) * BUFW + c0];
                const size_t base = ((size_t)(sbase + r0 + 8) * RDIM + r) * CE + c0;
                float2 ov;
                ov.x = d[nt][2] + bo0 + av.x;
                ov.y = d[nt][3] + bo1 + av.y;
                *(float2*)(out + base) = ov;
            }
        }
    }
}

// ============================================================================
extern "C" void kernel_launch(void* const* d_in, const int* in_sizes, int n_in,
                              void* d_out, int out_size) {
    const float* m      = (const float*)d_in[0];
    const float* mask   = (const float*)d_in[1];
    const float* Wq     = (const float*)d_in[2];
    const float* Wk     = (const float*)d_in[3];
    const float* Wv     = (const float*)d_in[4];
    const float* Wg     = (const float*)d_in[5];
    const float* bg     = (const float*)d_in[6];
    const float* Wo     = (const float*)d_in[7];
    const float* bo     = (const float*)d_in[8];
    const float* add_to = (const float*)d_in[9];
    float* out = (float*)d_out;

    cudaFuncSetAttribute(kv_kernel, cudaFuncAttributeMaxDynamicSharedMemorySize, KV_SMEM_BYTES);
    cudaFuncSetAttribute(gate_kernel, cudaFuncAttributeMaxDynamicSharedMemorySize, G_SMEM_BYTES);

    kv_kernel<<<KV_GRID, 128, KV_SMEM_BYTES>>>(m, mask, Wk, Wv);
    qk2_kernel<<<RDIM, 64>>>(Wq);
    attn3_kernel<<<dim3(NCH, RDIM), 256>>>(mask);
    combine2_kernel<<<RDIM, 64>>>();
    gate_kernel<<<G_GRID, 256, G_SMEM_BYTES>>>(m, Wg, bg, Wo, bo, add_to, out);
}

// round 10
// speedup vs baseline: 1.0114x; 1.0114x over previous
#include <cuda_runtime.h>
#include <cuda_bf16.h>
#include <cstdint>

typedef unsigned long long ull;
typedef unsigned int uint;

// ================= helpers =================
__device__ __forceinline__ void ffma2(ull& d, ull a, ull b) {
    asm("fma.rn.f32x2 %0, %1, %2, %0;" : "+l"(d) : "l"(a), "l"(b));
}
__device__ __forceinline__ ull pack2(float x, float y) {
    ull d; asm("mov.b64 %0, {%1, %2};" : "=l"(d) : "f"(x), "f"(y)); return d;
}
__device__ __forceinline__ float fast_sigmoid(float x) {
    float t;
    asm("tanh.approx.f32 %0, %1;" : "=f"(t) : "f"(x * 0.5f));
    return fmaf(t, 0.5f, 0.5f);
}
__device__ __forceinline__ uint bfpack(float x, float y) {
    __nv_bfloat16 bx = __float2bfloat16(x), by = __float2bfloat16(y);
    return (uint)__bfloat16_as_ushort(bx) | ((uint)__bfloat16_as_ushort(by) << 16);
}
__device__ __forceinline__ void split2(float x, float y, uint& hi, uint& lo) {
    __nv_bfloat16 hx = __float2bfloat16(x), hy = __float2bfloat16(y);
    hi = (uint)__bfloat16_as_ushort(hx) | ((uint)__bfloat16_as_ushort(hy) << 16);
    lo = bfpack(x - __bfloat162float(hx), y - __bfloat162float(hy));
}
__device__ __forceinline__ void mma_bf16(float* d, const uint* a, uint b0, uint b1) {
    asm volatile(
        "mma.sync.aligned.m16n8k16.row.col.f32.bf16.bf16.f32 "
        "{%0,%1,%2,%3}, {%4,%5,%6,%7}, {%8,%9}, {%0,%1,%2,%3};"
        : "+f"(d[0]), "+f"(d[1]), "+f"(d[2]), "+f"(d[3])
        : "r"(a[0]), "r"(a[1]), "r"(a[2]), "r"(a[3]), "r"(b0), "r"(b1));
}
__device__ __forceinline__ uint smem_u32(const void* p) {
    uint a;
    asm("{ .reg .u64 t; cvta.to.shared.u64 t, %1; cvt.u32.u64 %0, t; }" : "=r"(a) : "l"(p));
    return a;
}
__device__ __forceinline__ void cp_async16(uint saddr, const void* gptr) {
    asm volatile("cp.async.cg.shared.global [%0], [%1], 16;" :: "r"(saddr), "l"(gptr));
}
#define CP_COMMIT() asm volatile("cp.async.commit_group;" ::: "memory")
#define CP_WAIT0()  asm volatile("cp.async.wait_group 0;" ::: "memory")

// ================= constants =================
#define RDIM 384
#define SDIM 2048
#define CE   64
#define HC   64
#define QSCALE 0.35355339059327373f
#define NCH  8
#define CHUNK 256

// ================= scratch =================
__device__ float g_o[RDIM * HC];
__device__ float g_kv[(size_t)RDIM * SDIM * 16];
__device__ float g_poolq[RDIM * 64 * 64];
__device__ float g_poold[RDIM * 64];
__device__ float g_qproj[RDIM * 64];
__device__ float g_ov[RDIM * NCH * 64];
__device__ float g_mx[RDIM * NCH * 8];
__device__ float g_sm[RDIM * NCH * 8];

// ============================================================================
// K1: persistent pipelined kv projection + pooling partials. (round-8, passing)
// ============================================================================
#define KV_GRID 304
#define KV_NT   (RDIM * (SDIM / 128))
#define BUFW    68
#define ASTW    36
#define KV_BUF_FLOATS (128 * BUFW)
#define KV_W_OFF (2 * KV_BUF_FLOATS)
#define KV_SMEM_FLOATS (KV_W_OFF + 2 * 16 * ASTW)
#define KV_SMEM_BYTES  (KV_SMEM_FLOATS * 4)

__global__ void __launch_bounds__(128, 2)
kv_kernel(const float* __restrict__ m, const float* __restrict__ mask,
          const float* __restrict__ Wk, const float* __restrict__ Wv) {
    extern __shared__ __align__(16) float skf[];
    float* bufs[2] = { skf, skf + KV_BUF_FLOATS };
    uint* wkv_hi = (uint*)(skf + KV_W_OFF);
    uint* wkv_lo = wkv_hi + 16 * ASTW;

    const int tid  = threadIdx.x;
    const int lane = tid & 31;
    const int warp = tid >> 5;
    const int g    = lane >> 2;
    const int tg   = lane & 3;
    const int rowbase = warp * 32;

    const uint buf_u32[2] = { smem_u32(bufs[0]), smem_u32(bufs[1]) };

    for (int i = tid; i < 512; i += 128) {
        const int row = i >> 5, kp = i & 31;
        const float* W = (row < 8) ? (Wk + row * 64) : (Wv + (row - 8) * 64);
        float2 w = *(const float2*)(W + kp * 2);
        uint hi, lo; split2(w.x, w.y, hi, lo);
        wkv_hi[row * ASTW + kp] = hi;
        wkv_lo[row * ASTW + kp] = lo;
    }

    int t0 = blockIdx.x;
    {
        const int r = t0 >> 4, sbase = (t0 & 15) * 128;
#pragma unroll
        for (int i = 0; i < 16; i++) {
            const int idx = tid + 128 * i;
            const int row = idx >> 4;
            const int c4  = (idx & 15) * 4;
            cp_async16(buf_u32[0] + (uint)(row * BUFW + c4) * 4,
                       m + ((size_t)r * SDIM + sbase + row) * CE + c4);
        }
        CP_COMMIT();
    }

    int cur = 0;
#pragma unroll 1
    for (int t = t0; t < KV_NT; t += KV_GRID, cur ^= 1) {
        const int r     = t >> 4;
        const int ts    = t & 15;
        const int sbase = ts * 128;

        CP_WAIT0();
        __syncthreads();

        const int tn = t + KV_GRID;
        if (tn < KV_NT) {
            const int rn = tn >> 4, sbn = (tn & 15) * 128;
#pragma unroll
            for (int i = 0; i < 16; i++) {
                const int idx = tid + 128 * i;
                const int row = idx >> 4;
                const int c4  = (idx & 15) * 4;
                cp_async16(buf_u32[cur ^ 1] + (uint)(row * BUFW + c4) * 4,
                           m + ((size_t)rn * SDIM + sbn + row) * CE + c4);
            }
            CP_COMMIT();
        }

        const float* buf = bufs[cur];

        {
            const float mskv = mask[(size_t)r * SDIM + sbase + rowbase + lane];
            ull qn = 0ull;
            float qden = 0.0f;
#pragma unroll 8
            for (int i = 0; i < 32; i++) {
                const float msk = __shfl_sync(0xffffffffu, mskv, i);
                const ull mv = *(const ull*)&buf[(rowbase + i) * BUFW + 2 * lane];
                ffma2(qn, mv, pack2(msk, msk));
                qden += msk;
            }
            const int p = (r * 16 + ts) * 4 + warp;
            *(ull*)&g_poolq[(size_t)p * 64 + 2 * lane] = qn;
            if (lane == 0) g_poold[p] = qden;
        }

        float d[2][2][4];
#pragma unroll
        for (int mt = 0; mt < 2; mt++)
#pragma unroll
            for (int nt = 0; nt < 2; nt++)
#pragma unroll
                for (int q = 0; q < 4; q++) d[mt][nt][q] = 0.0f;

#pragma unroll
        for (int kt = 0; kt < 4; kt++) {
            uint ah[2][4], al[2][4];
#pragma unroll
            for (int mt = 0; mt < 2; mt++) {
                const int r0 = rowbase + mt * 16 + g;
                const float2 f0 = *(const float2*)&buf[r0 * BUFW + 16 * kt + 2 * tg];
                const float2 f1 = *(const float2*)&buf[(r0 + 8) * BUFW + 16 * kt + 2 * tg];
                const float2 f2 = *(const float2*)&buf[r0 * BUFW + 16 * kt + 2 * tg + 8];
                const float2 f3 = *(const float2*)&buf[(r0 + 8) * BUFW + 16 * kt + 2 * tg + 8];
                split2(f0.x, f0.y, ah[mt][0], al[mt][0]);
                split2(f1.x, f1.y, ah[mt][1], al[mt][1]);
                split2(f2.x, f2.y, ah[mt][2], al[mt][2]);
                split2(f3.x, f3.y, ah[mt][3], al[mt][3]);
            }
#pragma unroll
            for (int p = 0; p < 3; p++) {
                const uint* wb = (p == 1) ? wkv_lo : wkv_hi;
                const uint (*af)[4] = (p == 2) ? al : ah;
#pragma unroll
                for (int nt = 0; nt < 2; nt++) {
                    const uint b0 = wb[(nt * 8 + g) * ASTW + kt * 8 + tg];
                    const uint b1 = wb[(nt * 8 + g) * ASTW + kt * 8 + tg + 4];
                    mma_bf16(d[0][nt], af[0], b0, b1);
                    mma_bf16(d[1][nt], af[1], b0, b1);
                }
            }
        }

#pragma unroll
        for (int mt = 0; mt < 2; mt++) {
#pragma unroll
            for (int nt = 0; nt < 2; nt++) {
                const int c0 = nt * 8 + 2 * tg;
                const int r0 = rowbase + mt * 16 + g;
                *(float2*)&g_kv[((size_t)r * SDIM + sbase + r0) * 16 + c0] =
                    make_float2(d[mt][nt][0], d[mt][nt][1]);
                *(float2*)&g_kv[((size_t)r * SDIM + sbase + r0 + 8) * 16 + c0] =
                    make_float2(d[mt][nt][2], d[mt][nt][3]);
            }
        }
    }
}

// ============================================================================
// K2: reduce pooling partials -> q -> qproj. (unchanged)
// ============================================================================
__global__ void __launch_bounds__(64, 8)
qk2_kernel(const float* __restrict__ Wq) {
    __shared__ float qpool[64];
    const int r   = blockIdx.x;
    const int tid = threadIdx.x;

    float qs = 0.0f, qd = 0.0f;
#pragma unroll 8
    for (int p = 0; p < 64; p++) {
        qs += g_poolq[(size_t)(r * 64 + p) * 64 + tid];
        qd += g_poold[r * 64 + p];
    }
    qpool[tid] = qs / (qd + 1e-10f);
    __syncthreads();

    float acc = 0.0f;
    const float* wqr = Wq + tid * 64;
#pragma unroll
    for (int e = 0; e < 64; e++) acc = fmaf(qpool[e], wqr[e], acc);
    g_qproj[r * 64 + tid] = acc * QSCALE;
}

// ============================================================================
// K3: logits + chunk softmax partials + partial o. (unchanged)
// ============================================================================
__global__ void __launch_bounds__(256, 3)
attn3_kernel(const float* __restrict__ mask) {
    __shared__ float v_sh[256 * 9];
    __shared__ float a_sh[256 * 8];
    __shared__ float qp_sh[64];
    __shared__ float wred[64];
    __shared__ float mx_sh[8];

    const int tid  = threadIdx.x;
    const int lane = tid & 31;
    const int warp = tid >> 5;
    const int ch   = blockIdx.x;
    const int r    = blockIdx.y;
    const int sbase = ch * CHUNK;

    if (tid < 64) qp_sh[tid] = g_qproj[r * 64 + tid];

    const float* kvrow = &g_kv[((size_t)r * SDIM + sbase + tid) * 16];
    const float4 k01 = *(const float4*)(kvrow);
    const float4 k23 = *(const float4*)(kvrow + 4);
    const float4 v01 = *(const float4*)(kvrow + 8);
    const float4 v23 = *(const float4*)(kvrow + 12);
    float kreg[8] = { k01.x, k01.y, k01.z, k01.w, k23.x, k23.y, k23.z, k23.w };
    v_sh[tid * 9 + 0] = v01.x; v_sh[tid * 9 + 1] = v01.y;
    v_sh[tid * 9 + 2] = v01.z; v_sh[tid * 9 + 3] = v01.w;
    v_sh[tid * 9 + 4] = v23.x; v_sh[tid * 9 + 5] = v23.y;
    v_sh[tid * 9 + 6] = v23.z; v_sh[tid * 9 + 7] = v23.w;

    const float mymsk = mask[(size_t)r * SDIM + sbase + tid];
    __syncthreads();

    float lg[8];
    const float bias = (mymsk - 1.0f) * 1e9f;
#pragma unroll
    for (int h = 0; h < 8; h++) {
        float v = bias;
#pragma unroll
        for (int c = 0; c < 8; c++) v = fmaf(qp_sh[h * 8 + c], kreg[c], v);
        lg[h] = v;
    }

    float wm[8];
#pragma unroll
    for (int h = 0; h < 8; h++) {
        float v = lg[h];
#pragma unroll
        for (int off = 16; off > 0; off >>= 1)
            v = fmaxf(v, __shfl_xor_sync(0xffffffffu, v, off));
        wm[h] = v;
    }
    if (lane == 0)
#pragma unroll
        for (int h = 0; h < 8; h++) wred[warp * 8 + h] = wm[h];
    __syncthreads();
    if (tid < 8) {
        float v = -1e30f;
#pragma unroll
        for (int w = 0; w < 8; w++) v = fmaxf(v, wred[w * 8 + tid]);
        mx_sh[tid] = v;
    }
    __syncthreads();

    float sm[8];
#pragma unroll
    for (int h = 0; h < 8; h++) {
        const float e = __expf(lg[h] - mx_sh[h]);
        a_sh[tid * 8 + h] = e;
        float v = e;
#pragma unroll
        for (int off = 16; off > 0; off >>= 1)
            v += __shfl_xor_sync(0xffffffffu, v, off);
        sm[h] = v;
    }
    __syncthreads();
    if (lane == 0)
#pragma unroll
        for (int h = 0; h < 8; h++) wred[warp * 8 + h] = sm[h];
    __syncthreads();
    if (tid < 8) {
        float v = 0.0f;
#pragma unroll
        for (int w = 0; w < 8; w++) v += wred[w * 8 + tid];
        g_sm[(r * NCH + ch) * 8 + tid] = v;
        g_mx[(r * NCH + ch) * 8 + tid] = mx_sh[tid];
    }

    {
        const int h = warp;
        const int c = lane & 7;
        const int sgrp = lane >> 3;
        float acc = 0.0f;
#pragma unroll 8
        for (int i = 0; i < 64; i++) {
            const int row = 4 * i + sgrp;
            acc = fmaf(a_sh[row * 8 + h], v_sh[row * 9 + c], acc);
        }
        acc += __shfl_xor_sync(0xffffffffu, acc, 8);
        acc += __shfl_xor_sync(0xffffffffu, acc, 16);
        if (lane < 8)
            g_ov[(r * NCH + ch) * 64 + h * 8 + c] = acc;
    }
}

// ============================================================================
// C': combine chunks -> g_o. (unchanged)
// ============================================================================
__global__ void __launch_bounds__(64, 8)
combine2_kernel() {
    __shared__ float wgt[8][8];
    __shared__ float den[8];

    const int r   = blockIdx.x;
    const int tid = threadIdx.x;

    if (tid < 8) {
        const int h = tid;
        float mxg = -1e30f;
#pragma unroll
        for (int c = 0; c < NCH; c++) mxg = fmaxf(mxg, g_mx[(r * NCH + c) * 8 + h]);
        float d = 0.0f;
#pragma unroll
        for (int c = 0; c < NCH; c++) {
            const float w = __expf(g_mx[(r * NCH + c) * 8 + h] - mxg);
            wgt[h][c] = w;
            d = fmaf(g_sm[(r * NCH + c) * 8 + h], w, d);
        }
        den[h] = d;
    }
    __syncthreads();

    const int h = tid >> 3;
    float acc = 0.0f;
#pragma unroll
    for (int c = 0; c < NCH; c++)
        acc = fmaf(g_ov[(r * NCH + c) * 64 + tid], wgt[h][c], acc);
    g_o[r * HC + tid] = acc / den[h];
}

// ============================================================================
// Gate v4: persistent, 128 threads, 2 CTAs/SM, 64-row tiles.
// BOTH m and add_to double-buffered via cp.async -> no exposed epilogue LDG;
// second CTA hides barriers. t stays in registers between GEMMs.
// ============================================================================
#define G_GRID 304
#define G_ROWS 64
#define G_NT   (RDIM * (SDIM / G_ROWS))          // 12288
#define G_BUF_FLOATS (G_ROWS * BUFW)             // 4352
#define G_AB_OFF  (2 * G_BUF_FLOATS)
#define G_W_OFF   (4 * G_BUF_FLOATS)
#define G_SMEM_FLOATS (G_W_OFF + 4 * 64 * ASTW + 128)
#define G_SMEM_BYTES  (G_SMEM_FLOATS * 4)        // ~107 KB

__global__ void __launch_bounds__(128, 2)
gate_kernel(const float* __restrict__ m, const float* __restrict__ Wg,
            const float* __restrict__ bg, const float* __restrict__ Wo,
            const float* __restrict__ bo, const float* __restrict__ add_to,
            float* __restrict__ out) {
    extern __shared__ __align__(16) float sgf[];
    float* mbuf[2] = { sgf, sgf + G_BUF_FLOATS };
    float* abuf[2] = { sgf + G_AB_OFF, sgf + G_AB_OFF + G_BUF_FLOATS };
    uint* wg_hi = (uint*)(sgf + G_W_OFF);
    uint* wg_lo = wg_hi + 64 * ASTW;
    uint* wo_hi = wg_lo + 64 * ASTW;
    uint* wo_lo = wo_hi + 64 * ASTW;
    float* bg_sh = (float*)(wo_lo + 64 * ASTW);
    float* bo_sh = bg_sh + 64;

    const int tid  = threadIdx.x;
    const int lane = tid & 31;
    const int warp = tid >> 5;
    const int g    = lane >> 2;
    const int tg   = lane & 3;
    const int rowbase = warp * 16;     // 4 warps x 16 rows = 64

    const uint mbuf_u32[2] = { smem_u32(mbuf[0]), smem_u32(mbuf[1]) };
    const uint abuf_u32[2] = { smem_u32(abuf[0]), smem_u32(abuf[1]) };

    // ---- stage weights + biases ONCE ----
    for (int i = tid; i < 2048; i += 128) {
        const int row = i >> 5, kp = i & 31;
        {
            float2 w = *(const float2*)(Wg + row * 64 + kp * 2);
            uint hi, lo; split2(w.x, w.y, hi, lo);
            wg_hi[row * ASTW + kp] = hi;
            wg_lo[row * ASTW + kp] = lo;
        }
        {
            float2 w = *(const float2*)(Wo + row * 64 + kp * 2);
            uint hi, lo; split2(w.x, w.y, hi, lo);
            wo_hi[row * ASTW + kp] = hi;
            wo_lo[row * ASTW + kp] = lo;
        }
    }
    if (tid < 64) {
        bg_sh[tid] = bg[tid];
        bo_sh[tid] = bo[tid];
    }

    // ---- prefetch helper: m 64-row tile + add_to tile into stage st ----
    auto prefetch = [&](int t, int st) {
        const int r = t >> 5, sbase = (t & 31) * G_ROWS;
#pragma unroll
        for (int i = 0; i < 8; i++) {
            const int idx = tid + 128 * i;
            const int row = idx >> 4;
            const int c4  = (idx & 15) * 4;
            cp_async16(mbuf_u32[st] + (uint)(row * BUFW + c4) * 4,
                       m + ((size_t)r * SDIM + sbase + row) * CE + c4);
        }
#pragma unroll
        for (int i = 0; i < 8; i++) {
            const int idx = tid + 128 * i;
            const int row = idx >> 4;
            const int c4  = (idx & 15) * 4;
            cp_async16(abuf_u32[st] + (uint)(row * BUFW + c4) * 4,
                       add_to + ((size_t)(sbase + row) * RDIM + r) * CE + c4);
        }
        CP_COMMIT();
    };

    const int t0 = blockIdx.x;
    if (t0 < G_NT) prefetch(t0, 0);

    int cur = 0;
#pragma unroll 1
    for (int t = t0; t < G_NT; t += G_GRID, cur ^= 1) {
        const int r     = t >> 5;
        const int sbase = (t & 31) * G_ROWS;

        CP_WAIT0();
        __syncthreads();

        const int tn = t + G_GRID;
        if (tn < G_NT) prefetch(tn, cur ^ 1);

        const float* buf = mbuf[cur];
        float d[8][4];

        // ===== GEMM1: gate logits = m @ Wg^T =====
#pragma unroll
        for (int nt = 0; nt < 8; nt++)
#pragma unroll
            for (int q = 0; q < 4; q++) d[nt][q] = 0.0f;

#pragma unroll
        for (int kt = 0; kt < 4; kt++) {
            uint ah[4], al[4];
            {
                const int r0 = rowbase + g;
                const float2 f0 = *(const float2*)&buf[r0 * BUFW + 16 * kt + 2 * tg];
                const float2 f1 = *(const float2*)&buf[(r0 + 8) * BUFW + 16 * kt + 2 * tg];
                const float2 f2 = *(const float2*)&buf[r0 * BUFW + 16 * kt + 2 * tg + 8];
                const float2 f3 = *(const float2*)&buf[(r0 + 8) * BUFW + 16 * kt + 2 * tg + 8];
                split2(f0.x, f0.y, ah[0], al[0]);
                split2(f1.x, f1.y, ah[1], al[1]);
                split2(f2.x, f2.y, ah[2], al[2]);
                split2(f3.x, f3.y, ah[3], al[3]);
            }
#pragma unroll
            for (int p = 0; p < 3; p++) {
                const uint* wb = (p == 1) ? wg_lo : wg_hi;
                const uint* af = (p == 2) ? al : ah;
#pragma unroll
                for (int nt = 0; nt < 8; nt++) {
                    const uint b0 = wb[(nt * 8 + g) * ASTW + kt * 8 + tg];
                    const uint b1 = wb[(nt * 8 + g) * ASTW + kt * 8 + tg + 4];
                    mma_bf16(d[nt], af, b0, b1);
                }
            }
        }

        // ===== epilogue 1 (registers): t = sigmoid(d+bg)*o =====
        uint th[8][2], tl[8][2];
#pragma unroll
        for (int nt = 0; nt < 8; nt++) {
            const int c0 = nt * 8 + tg * 2;
            const float ov0 = __ldg(&g_o[r * HC + c0]);
            const float ov1 = __ldg(&g_o[r * HC + c0 + 1]);
            const float bg0 = bg_sh[c0], bg1 = bg_sh[c0 + 1];
            const float t0v = fast_sigmoid(d[nt][0] + bg0) * ov0;
            const float t1v = fast_sigmoid(d[nt][1] + bg1) * ov1;
            const float t2v = fast_sigmoid(d[nt][2] + bg0) * ov0;
            const float t3v = fast_sigmoid(d[nt][3] + bg1) * ov1;
            split2(t0v, t1v, th[nt][0], tl[nt][0]);
            split2(t2v, t3v, th[nt][1], tl[nt][1]);
        }

        // ===== GEMM2: out = t @ Wo^T =====
#pragma unroll
        for (int nt = 0; nt < 8; nt++)
#pragma unroll
            for (int q = 0; q < 4; q++) d[nt][q] = 0.0f;

#pragma unroll
        for (int p = 0; p < 3; p++) {
            const uint* wb = (p == 1) ? wo_lo : wo_hi;
#pragma unroll
            for (int kt = 0; kt < 4; kt++) {
                uint a[4];
                if (p == 2) {
                    a[0] = tl[2 * kt][0]; a[1] = tl[2 * kt][1];
                    a[2] = tl[2 * kt + 1][0]; a[3] = tl[2 * kt + 1][1];
                } else {
                    a[0] = th[2 * kt][0]; a[1] = th[2 * kt][1];
                    a[2] = th[2 * kt + 1][0]; a[3] = th[2 * kt + 1][1];
                }
#pragma unroll
                for (int nt = 0; nt < 8; nt++) {
                    const uint b0 = wb[(nt * 8 + g) * ASTW + kt * 8 + tg];
                    const uint b1 = wb[(nt * 8 + g) * ASTW + kt * 8 + tg + 4];
                    mma_bf16(d[nt], a, b0, b1);
                }
            }
        }

        // ===== epilogue 2: out = D + bo + add_to(smem) =====
        const float* ab = abuf[cur];
#pragma unroll
        for (int nt = 0; nt < 8; nt++) {
            const int c0 = nt * 8 + tg * 2;
            const float bo0 = bo_sh[c0], bo1 = bo_sh[c0 + 1];
            const int r0 = rowbase + g;
            {
                const float2 av = *(const float2*)&ab[r0 * BUFW + c0];
                const size_t base = ((size_t)(sbase + r0) * RDIM + r) * CE + c0;
                float2 ov;
                ov.x = d[nt][0] + bo0 + av.x;
                ov.y = d[nt][1] + bo1 + av.y;
                *(float2*)(out + base) = ov;
            }
            {
                const float2 av = *(const float2*)&ab[(r0 + 8) * BUFW + c0];
                const size_t base = ((size_t)(sbase + r0 + 8) * RDIM + r) * CE + c0;
                float2 ov;
                ov.x = d[nt][2] + bo0 + av.x;
                ov.y = d[nt][3] + bo1 + av.y;
                *(float2*)(out + base) = ov;
            }
        }
    }
}

// ============================================================================
extern "C" void kernel_launch(void* const* d_in, const int* in_sizes, int n_in,
                              void* d_out, int out_size) {
    const float* m      = (const float*)d_in[0];
    const float* mask   = (const float*)d_in[1];
    const float* Wq     = (const float*)d_in[2];
    const float* Wk     = (const float*)d_in[3];
    const float* Wv     = (const float*)d_in[4];
    const float* Wg     = (const float*)d_in[5];
    const float* bg     = (const float*)d_in[6];
    const float* Wo     = (const float*)d_in[7];
    const float* bo     = (const float*)d_in[8];
    const float* add_to = (const float*)d_in[9];
    float* out = (float*)d_out;

    cudaFuncSetAttribute(kv_kernel, cudaFuncAttributeMaxDynamicSharedMemorySize, KV_SMEM_BYTES);
    cudaFuncSetAttribute(gate_kernel, cudaFuncAttributeMaxDynamicSharedMemorySize, G_SMEM_BYTES);

    kv_kernel<<<KV_GRID, 128, KV_SMEM_BYTES>>>(m, mask, Wk, Wv);
    qk2_kernel<<<RDIM, 64>>>(Wq);
    attn3_kernel<<<dim3(NCH, RDIM), 256>>>(mask);
    combine2_kernel<<<RDIM, 64>>>();
    gate_kernel<<<G_GRID, 128, G_SMEM_BYTES>>>(m, Wg, bg, Wo, bo, add_to, out);
}

// round 11
// speedup vs baseline: 1.0638x; 1.0519x over previous
#include <cuda_runtime.h>
#include <cuda_bf16.h>
#include <cstdint>

typedef unsigned long long ull;
typedef unsigned int uint;

// ================= helpers =================
__device__ __forceinline__ void ffma2(ull& d, ull a, ull b) {
    asm("fma.rn.f32x2 %0, %1, %2, %0;" : "+l"(d) : "l"(a), "l"(b));
}
__device__ __forceinline__ ull pack2(float x, float y) {
    ull d; asm("mov.b64 %0, {%1, %2};" : "=l"(d) : "f"(x), "f"(y)); return d;
}
__device__ __forceinline__ float fast_sigmoid(float x) {
    float t;
    asm("tanh.approx.f32 %0, %1;" : "=f"(t) : "f"(x * 0.5f));
    return fmaf(t, 0.5f, 0.5f);
}
__device__ __forceinline__ uint bfpack(float x, float y) {
    __nv_bfloat16 bx = __float2bfloat16(x), by = __float2bfloat16(y);
    return (uint)__bfloat16_as_ushort(bx) | ((uint)__bfloat16_as_ushort(by) << 16);
}
__device__ __forceinline__ void split2(float x, float y, uint& hi, uint& lo) {
    __nv_bfloat16 hx = __float2bfloat16(x), hy = __float2bfloat16(y);
    hi = (uint)__bfloat16_as_ushort(hx) | ((uint)__bfloat16_as_ushort(hy) << 16);
    lo = bfpack(x - __bfloat162float(hx), y - __bfloat162float(hy));
}
__device__ __forceinline__ void mma_bf16(float* d, const uint* a, uint b0, uint b1) {
    asm volatile(
        "mma.sync.aligned.m16n8k16.row.col.f32.bf16.bf16.f32 "
        "{%0,%1,%2,%3}, {%4,%5,%6,%7}, {%8,%9}, {%0,%1,%2,%3};"
        : "+f"(d[0]), "+f"(d[1]), "+f"(d[2]), "+f"(d[3])
        : "r"(a[0]), "r"(a[1]), "r"(a[2]), "r"(a[3]), "r"(b0), "r"(b1));
}
__device__ __forceinline__ uint smem_u32(const void* p) {
    uint a;
    asm("{ .reg .u64 t; cvta.to.shared.u64 t, %1; cvt.u32.u64 %0, t; }" : "=r"(a) : "l"(p));
    return a;
}
__device__ __forceinline__ void cp_async16(uint saddr, const void* gptr) {
    asm volatile("cp.async.cg.shared.global [%0], [%1], 16;" :: "r"(saddr), "l"(gptr));
}
#define CP_COMMIT() asm volatile("cp.async.commit_group;" ::: "memory")
#define CP_WAIT0()  asm volatile("cp.async.wait_group 0;" ::: "memory")

// ================= constants =================
#define RDIM 384
#define SDIM 2048
#define CE   64
#define HC   64
#define QSCALE 0.35355339059327373f
#define NCH  8
#define CHUNK 256

// ================= scratch =================
__device__ float g_o[RDIM * HC];
__device__ float g_kv[(size_t)RDIM * SDIM * 16];
__device__ float g_poolq[RDIM * 64 * 64];
__device__ float g_poold[RDIM * 64];
__device__ float g_qproj[RDIM * 64];
__device__ float g_ov[RDIM * NCH * 64];
__device__ float g_mx[RDIM * NCH * 8];
__device__ float g_sm[RDIM * NCH * 8];

// ============================================================================
// K1: persistent pipelined kv projection + pooling partials.
// Round-8 structure; CONTIGUOUS tile ranges per CTA for DRAM locality.
// ============================================================================
#define KV_GRID 304
#define KV_NT   (RDIM * (SDIM / 128))
#define BUFW    68
#define ASTW    36
#define KV_BUF_FLOATS (128 * BUFW)
#define KV_W_OFF (2 * KV_BUF_FLOATS)
#define KV_SMEM_FLOATS (KV_W_OFF + 2 * 16 * ASTW)
#define KV_SMEM_BYTES  (KV_SMEM_FLOATS * 4)

__global__ void __launch_bounds__(128, 2)
kv_kernel(const float* __restrict__ m, const float* __restrict__ mask,
          const float* __restrict__ Wk, const float* __restrict__ Wv) {
    extern __shared__ __align__(16) float skf[];
    float* bufs[2] = { skf, skf + KV_BUF_FLOATS };
    uint* wkv_hi = (uint*)(skf + KV_W_OFF);
    uint* wkv_lo = wkv_hi + 16 * ASTW;

    const int tid  = threadIdx.x;
    const int lane = tid & 31;
    const int warp = tid >> 5;
    const int g    = lane >> 2;
    const int tg   = lane & 3;
    const int rowbase = warp * 32;

    const uint buf_u32[2] = { smem_u32(bufs[0]), smem_u32(bufs[1]) };

    for (int i = tid; i < 512; i += 128) {
        const int row = i >> 5, kp = i & 31;
        const float* W = (row < 8) ? (Wk + row * 64) : (Wv + (row - 8) * 64);
        float2 w = *(const float2*)(W + kp * 2);
        uint hi, lo; split2(w.x, w.y, hi, lo);
        wkv_hi[row * ASTW + kp] = hi;
        wkv_lo[row * ASTW + kp] = lo;
    }

    // contiguous tile range for this CTA
    const int per = KV_NT / KV_GRID;             // 20
    const int rem = KV_NT % KV_GRID;             // 64
    const int b   = blockIdx.x;
    const int tstart = b * per + (b < rem ? b : rem);
    const int tend   = tstart + per + (b < rem ? 1 : 0);

    {
        const int r = tstart >> 4, sbase = (tstart & 15) * 128;
#pragma unroll
        for (int i = 0; i < 16; i++) {
            const int idx = tid + 128 * i;
            const int row = idx >> 4;
            const int c4  = (idx & 15) * 4;
            cp_async16(buf_u32[0] + (uint)(row * BUFW + c4) * 4,
                       m + ((size_t)r * SDIM + sbase + row) * CE + c4);
        }
        CP_COMMIT();
    }

    int cur = 0;
#pragma unroll 1
    for (int t = tstart; t < tend; t++, cur ^= 1) {
        const int r     = t >> 4;
        const int ts    = t & 15;
        const int sbase = ts * 128;

        CP_WAIT0();
        __syncthreads();

        const int tn = t + 1;
        if (tn < tend) {
            const int rn = tn >> 4, sbn = (tn & 15) * 128;
#pragma unroll
            for (int i = 0; i < 16; i++) {
                const int idx = tid + 128 * i;
                const int row = idx >> 4;
                const int c4  = (idx & 15) * 4;
                cp_async16(buf_u32[cur ^ 1] + (uint)(row * BUFW + c4) * 4,
                           m + ((size_t)rn * SDIM + sbn + row) * CE + c4);
            }
            CP_COMMIT();
        }

        const float* buf = bufs[cur];

        {
            const float mskv = mask[(size_t)r * SDIM + sbase + rowbase + lane];
            ull qn = 0ull;
            float qden = 0.0f;
#pragma unroll 8
            for (int i = 0; i < 32; i++) {
                const float msk = __shfl_sync(0xffffffffu, mskv, i);
                const ull mv = *(const ull*)&buf[(rowbase + i) * BUFW + 2 * lane];
                ffma2(qn, mv, pack2(msk, msk));
                qden += msk;
            }
            const int p = (r * 16 + ts) * 4 + warp;
            *(ull*)&g_poolq[(size_t)p * 64 + 2 * lane] = qn;
            if (lane == 0) g_poold[p] = qden;
        }

        float d[2][2][4];
#pragma unroll
        for (int mt = 0; mt < 2; mt++)
#pragma unroll
            for (int nt = 0; nt < 2; nt++)
#pragma unroll
                for (int q = 0; q < 4; q++) d[mt][nt][q] = 0.0f;

#pragma unroll
        for (int kt = 0; kt < 4; kt++) {
            uint ah[2][4], al[2][4];
#pragma unroll
            for (int mt = 0; mt < 2; mt++) {
                const int r0 = rowbase + mt * 16 + g;
                const float2 f0 = *(const float2*)&buf[r0 * BUFW + 16 * kt + 2 * tg];
                const float2 f1 = *(const float2*)&buf[(r0 + 8) * BUFW + 16 * kt + 2 * tg];
                const float2 f2 = *(const float2*)&buf[r0 * BUFW + 16 * kt + 2 * tg + 8];
                const float2 f3 = *(const float2*)&buf[(r0 + 8) * BUFW + 16 * kt + 2 * tg + 8];
                split2(f0.x, f0.y, ah[mt][0], al[mt][0]);
                split2(f1.x, f1.y, ah[mt][1], al[mt][1]);
                split2(f2.x, f2.y, ah[mt][2], al[mt][2]);
                split2(f3.x, f3.y, ah[mt][3], al[mt][3]);
            }
#pragma unroll
            for (int p = 0; p < 3; p++) {
                const uint* wb = (p == 1) ? wkv_lo : wkv_hi;
                const uint (*af)[4] = (p == 2) ? al : ah;
#pragma unroll
                for (int nt = 0; nt < 2; nt++) {
                    const uint b0 = wb[(nt * 8 + g) * ASTW + kt * 8 + tg];
                    const uint b1 = wb[(nt * 8 + g) * ASTW + kt * 8 + tg + 4];
                    mma_bf16(d[0][nt], af[0], b0, b1);
                    mma_bf16(d[1][nt], af[1], b0, b1);
                }
            }
        }

#pragma unroll
        for (int mt = 0; mt < 2; mt++) {
#pragma unroll
            for (int nt = 0; nt < 2; nt++) {
                const int c0 = nt * 8 + 2 * tg;
                const int r0 = rowbase + mt * 16 + g;
                *(float2*)&g_kv[((size_t)r * SDIM + sbase + r0) * 16 + c0] =
                    make_float2(d[mt][nt][0], d[mt][nt][1]);
                *(float2*)&g_kv[((size_t)r * SDIM + sbase + r0 + 8) * 16 + c0] =
                    make_float2(d[mt][nt][2], d[mt][nt][3]);
            }
        }
    }
}

// ============================================================================
// K2: reduce pooling partials -> q -> qproj. (unchanged)
// ============================================================================
__global__ void __launch_bounds__(64, 8)
qk2_kernel(const float* __restrict__ Wq) {
    __shared__ float qpool[64];
    const int r   = blockIdx.x;
    const int tid = threadIdx.x;

    float qs = 0.0f, qd = 0.0f;
#pragma unroll 8
    for (int p = 0; p < 64; p++) {
        qs += g_poolq[(size_t)(r * 64 + p) * 64 + tid];
        qd += g_poold[r * 64 + p];
    }
    qpool[tid] = qs / (qd + 1e-10f);
    __syncthreads();

    float acc = 0.0f;
    const float* wqr = Wq + tid * 64;
#pragma unroll
    for (int e = 0; e < 64; e++) acc = fmaf(qpool[e], wqr[e], acc);
    g_qproj[r * 64 + tid] = acc * QSCALE;
}

// ============================================================================
// K3: logits + chunk softmax partials + partial o. (occupancy 3 -> 6)
// ============================================================================
__global__ void __launch_bounds__(256, 6)
attn3_kernel(const float* __restrict__ mask) {
    __shared__ float v_sh[256 * 9];
    __shared__ float a_sh[256 * 8];
    __shared__ float qp_sh[64];
    __shared__ float wred[64];
    __shared__ float mx_sh[8];

    const int tid  = threadIdx.x;
    const int lane = tid & 31;
    const int warp = tid >> 5;
    const int ch   = blockIdx.x;
    const int r    = blockIdx.y;
    const int sbase = ch * CHUNK;

    if (tid < 64) qp_sh[tid] = g_qproj[r * 64 + tid];

    const float* kvrow = &g_kv[((size_t)r * SDIM + sbase + tid) * 16];
    const float4 k01 = *(const float4*)(kvrow);
    const float4 k23 = *(const float4*)(kvrow + 4);
    const float4 v01 = *(const float4*)(kvrow + 8);
    const float4 v23 = *(const float4*)(kvrow + 12);
    float kreg[8] = { k01.x, k01.y, k01.z, k01.w, k23.x, k23.y, k23.z, k23.w };
    v_sh[tid * 9 + 0] = v01.x; v_sh[tid * 9 + 1] = v01.y;
    v_sh[tid * 9 + 2] = v01.z; v_sh[tid * 9 + 3] = v01.w;
    v_sh[tid * 9 + 4] = v23.x; v_sh[tid * 9 + 5] = v23.y;
    v_sh[tid * 9 + 6] = v23.z; v_sh[tid * 9 + 7] = v23.w;

    const float mymsk = mask[(size_t)r * SDIM + sbase + tid];
    __syncthreads();

    float lg[8];
    const float bias = (mymsk - 1.0f) * 1e9f;
#pragma unroll
    for (int h = 0; h < 8; h++) {
        float v = bias;
#pragma unroll
        for (int c = 0; c < 8; c++) v = fmaf(qp_sh[h * 8 + c], kreg[c], v);
        lg[h] = v;
    }

    float wm[8];
#pragma unroll
    for (int h = 0; h < 8; h++) {
        float v = lg[h];
#pragma unroll
        for (int off = 16; off > 0; off >>= 1)
            v = fmaxf(v, __shfl_xor_sync(0xffffffffu, v, off));
        wm[h] = v;
    }
    if (lane == 0)
#pragma unroll
        for (int h = 0; h < 8; h++) wred[warp * 8 + h] = wm[h];
    __syncthreads();
    if (tid < 8) {
        float v = -1e30f;
#pragma unroll
        for (int w = 0; w < 8; w++) v = fmaxf(v, wred[w * 8 + tid]);
        mx_sh[tid] = v;
    }
    __syncthreads();

    float sm[8];
#pragma unroll
    for (int h = 0; h < 8; h++) {
        const float e = __expf(lg[h] - mx_sh[h]);
        a_sh[tid * 8 + h] = e;
        float v = e;
#pragma unroll
        for (int off = 16; off > 0; off >>= 1)
            v += __shfl_xor_sync(0xffffffffu, v, off);
        sm[h] = v;
    }
    __syncthreads();
    if (lane == 0)
#pragma unroll
        for (int h = 0; h < 8; h++) wred[warp * 8 + h] = sm[h];
    __syncthreads();
    if (tid < 8) {
        float v = 0.0f;
#pragma unroll
        for (int w = 0; w < 8; w++) v += wred[w * 8 + tid];
        g_sm[(r * NCH + ch) * 8 + tid] = v;
        g_mx[(r * NCH + ch) * 8 + tid] = mx_sh[tid];
    }

    {
        const int h = warp;
        const int c = lane & 7;
        const int sgrp = lane >> 3;
        float acc = 0.0f;
#pragma unroll 8
        for (int i = 0; i < 64; i++) {
            const int row = 4 * i + sgrp;
            acc = fmaf(a_sh[row * 8 + h], v_sh[row * 9 + c], acc);
        }
        acc += __shfl_xor_sync(0xffffffffu, acc, 8);
        acc += __shfl_xor_sync(0xffffffffu, acc, 16);
        if (lane < 8)
            g_ov[(r * NCH + ch) * 64 + h * 8 + c] = acc;
    }
}

// ============================================================================
// C': combine chunks -> g_o. (unchanged)
// ============================================================================
__global__ void __launch_bounds__(64, 8)
combine2_kernel() {
    __shared__ float wgt[8][8];
    __shared__ float den[8];

    const int r   = blockIdx.x;
    const int tid = threadIdx.x;

    if (tid < 8) {
        const int h = tid;
        float mxg = -1e30f;
#pragma unroll
        for (int c = 0; c < NCH; c++) mxg = fmaxf(mxg, g_mx[(r * NCH + c) * 8 + h]);
        float d = 0.0f;
#pragma unroll
        for (int c = 0; c < NCH; c++) {
            const float w = __expf(g_mx[(r * NCH + c) * 8 + h] - mxg);
            wgt[h][c] = w;
            d = fmaf(g_sm[(r * NCH + c) * 8 + h], w, d);
        }
        den[h] = d;
    }
    __syncthreads();

    const int h = tid >> 3;
    float acc = 0.0f;
#pragma unroll
    for (int c = 0; c < NCH; c++)
        acc = fmaf(g_ov[(r * NCH + c) * 64 + tid], wgt[h][c], acc);
    g_o[r * HC + tid] = acc / den[h];
}

// ============================================================================
// Gate (round-8 exact structure: 128 thr, 2 CTA/SM, 128-row tiles, m-only
// cp.async double buffer, add_to via LDG in epilogue) with CONTIGUOUS tile
// ranges per CTA.
// ============================================================================
#define G_GRID 304
#define G_NT   (RDIM * (SDIM / 128))
#define G_BUF_FLOATS (128 * BUFW)
#define G_W_OFF  (2 * G_BUF_FLOATS)
#define G_SMEM_FLOATS (G_W_OFF + 4 * 64 * ASTW + 128)
#define G_SMEM_BYTES  (G_SMEM_FLOATS * 4)

__global__ void __launch_bounds__(128, 2)
gate_kernel(const float* __restrict__ m, const float* __restrict__ Wg,
            const float* __restrict__ bg, const float* __restrict__ Wo,
            const float* __restrict__ bo, const float* __restrict__ add_to,
            float* __restrict__ out) {
    extern __shared__ __align__(16) float sgf[];
    float* bufs[2] = { sgf, sgf + G_BUF_FLOATS };
    uint* wg_hi = (uint*)(sgf + G_W_OFF);
    uint* wg_lo = wg_hi + 64 * ASTW;
    uint* wo_hi = wg_lo + 64 * ASTW;
    uint* wo_lo = wo_hi + 64 * ASTW;
    float* bg_sh = (float*)(wo_lo + 64 * ASTW);
    float* bo_sh = bg_sh + 64;

    const int tid  = threadIdx.x;
    const int lane = tid & 31;
    const int warp = tid >> 5;
    const int g    = lane >> 2;
    const int tg   = lane & 3;
    const int rowbase = warp * 32;

    const uint buf_u32[2] = { smem_u32(bufs[0]), smem_u32(bufs[1]) };

    for (int i = tid; i < 2048; i += 128) {
        const int row = i >> 5, kp = i & 31;
        {
            float2 w = *(const float2*)(Wg + row * 64 + kp * 2);
            uint hi, lo; split2(w.x, w.y, hi, lo);
            wg_hi[row * ASTW + kp] = hi;
            wg_lo[row * ASTW + kp] = lo;
        }
        {
            float2 w = *(const float2*)(Wo + row * 64 + kp * 2);
            uint hi, lo; split2(w.x, w.y, hi, lo);
            wo_hi[row * ASTW + kp] = hi;
            wo_lo[row * ASTW + kp] = lo;
        }
    }
    if (tid < 64) {
        bg_sh[tid] = bg[tid];
        bo_sh[tid] = bo[tid];
    }

    // contiguous tile range
    const int per = G_NT / G_GRID;               // 20
    const int rem = G_NT % G_GRID;               // 64
    const int b   = blockIdx.x;
    const int tstart = b * per + (b < rem ? b : rem);
    const int tend   = tstart + per + (b < rem ? 1 : 0);

    {
        const int r = tstart >> 4, sbase = (tstart & 15) * 128;
#pragma unroll
        for (int i = 0; i < 16; i++) {
            const int idx = tid + 128 * i;
            const int row = idx >> 4;
            const int c4  = (idx & 15) * 4;
            cp_async16(buf_u32[0] + (uint)(row * BUFW + c4) * 4,
                       m + ((size_t)r * SDIM + sbase + row) * CE + c4);
        }
        CP_COMMIT();
    }

    int cur = 0;
#pragma unroll 1
    for (int t = tstart; t < tend; t++, cur ^= 1) {
        const int r     = t >> 4;
        const int sbase = (t & 15) * 128;

        CP_WAIT0();
        __syncthreads();

        const int tn = t + 1;
        if (tn < tend) {
            const int rn = tn >> 4, sbn = (tn & 15) * 128;
#pragma unroll
            for (int i = 0; i < 16; i++) {
                const int idx = tid + 128 * i;
                const int row = idx >> 4;
                const int c4  = (idx & 15) * 4;
                cp_async16(buf_u32[cur ^ 1] + (uint)(row * BUFW + c4) * 4,
                           m + ((size_t)rn * SDIM + sbn + row) * CE + c4);
            }
            CP_COMMIT();
        }

        const float* buf = bufs[cur];
        float d[2][8][4];

        // ===== GEMM1: gate logits = m @ Wg^T =====
#pragma unroll
        for (int mt = 0; mt < 2; mt++)
#pragma unroll
            for (int nt = 0; nt < 8; nt++)
#pragma unroll
                for (int q = 0; q < 4; q++) d[mt][nt][q] = 0.0f;

#pragma unroll
        for (int kt = 0; kt < 4; kt++) {
            uint ah[2][4], al[2][4];
#pragma unroll
            for (int mt = 0; mt < 2; mt++) {
                const int r0 = rowbase + mt * 16 + g;
                const float2 f0 = *(const float2*)&buf[r0 * BUFW + 16 * kt + 2 * tg];
                const float2 f1 = *(const float2*)&buf[(r0 + 8) * BUFW + 16 * kt + 2 * tg];
                const float2 f2 = *(const float2*)&buf[r0 * BUFW + 16 * kt + 2 * tg + 8];
                const float2 f3 = *(const float2*)&buf[(r0 + 8) * BUFW + 16 * kt + 2 * tg + 8];
                split2(f0.x, f0.y, ah[mt][0], al[mt][0]);
                split2(f1.x, f1.y, ah[mt][1], al[mt][1]);
                split2(f2.x, f2.y, ah[mt][2], al[mt][2]);
                split2(f3.x, f3.y, ah[mt][3], al[mt][3]);
            }
#pragma unroll
            for (int p = 0; p < 3; p++) {
                const uint* wb = (p == 1) ? wg_lo : wg_hi;
                const uint (*af)[4] = (p == 2) ? al : ah;
#pragma unroll
                for (int nt = 0; nt < 8; nt++) {
                    const uint b0 = wb[(nt * 8 + g) * ASTW + kt * 8 + tg];
                    const uint b1 = wb[(nt * 8 + g) * ASTW + kt * 8 + tg + 4];
                    mma_bf16(d[0][nt], af[0], b0, b1);
                    mma_bf16(d[1][nt], af[1], b0, b1);
                }
            }
        }

        // ===== epilogue 1 (registers): t = sigmoid(d+bg)*o =====
        uint th[2][8][2], tl[2][8][2];
        {
            float ov0[8], ov1[8];
#pragma unroll
            for (int nt = 0; nt < 8; nt++) {
                const int c0 = nt * 8 + tg * 2;
                ov0[nt] = __ldg(&g_o[r * HC + c0]);
                ov1[nt] = __ldg(&g_o[r * HC + c0 + 1]);
            }
#pragma unroll
            for (int mt = 0; mt < 2; mt++) {
#pragma unroll
                for (int nt = 0; nt < 8; nt++) {
                    const int c0 = nt * 8 + tg * 2;
                    const float bg0 = bg_sh[c0], bg1 = bg_sh[c0 + 1];
                    const float t0 = fast_sigmoid(d[mt][nt][0] + bg0) * ov0[nt];
                    const float t1 = fast_sigmoid(d[mt][nt][1] + bg1) * ov1[nt];
                    const float t2 = fast_sigmoid(d[mt][nt][2] + bg0) * ov0[nt];
                    const float t3 = fast_sigmoid(d[mt][nt][3] + bg1) * ov1[nt];
                    split2(t0, t1, th[mt][nt][0], tl[mt][nt][0]);
                    split2(t2, t3, th[mt][nt][1], tl[mt][nt][1]);
                }
            }
        }

        // ===== GEMM2: out = t @ Wo^T =====
#pragma unroll
        for (int mt = 0; mt < 2; mt++)
#pragma unroll
            for (int nt = 0; nt < 8; nt++)
#pragma unroll
                for (int q = 0; q < 4; q++) d[mt][nt][q] = 0.0f;

#pragma unroll
        for (int p = 0; p < 3; p++) {
            const uint* wb = (p == 1) ? wo_lo : wo_hi;
#pragma unroll
            for (int kt = 0; kt < 4; kt++) {
                uint a[2][4];
#pragma unroll
                for (int mt = 0; mt < 2; mt++) {
                    if (p == 2) {
                        a[mt][0] = tl[mt][2 * kt][0];
                        a[mt][1] = tl[mt][2 * kt][1];
                        a[mt][2] = tl[mt][2 * kt + 1][0];
                        a[mt][3] = tl[mt][2 * kt + 1][1];
                    } else {
                        a[mt][0] = th[mt][2 * kt][0];
                        a[mt][1] = th[mt][2 * kt][1];
                        a[mt][2] = th[mt][2 * kt + 1][0];
                        a[mt][3] = th[mt][2 * kt + 1][1];
                    }
                }
#pragma unroll
                for (int nt = 0; nt < 8; nt++) {
                    const uint b0 = wb[(nt * 8 + g) * ASTW + kt * 8 + tg];
                    const uint b1 = wb[(nt * 8 + g) * ASTW + kt * 8 + tg + 4];
                    mma_bf16(d[0][nt], a[0], b0, b1);
                    mma_bf16(d[1][nt], a[1], b0, b1);
                }
            }
        }

        // ===== epilogue 2: out[s][r][:] = D + bo + add_to =====
#pragma unroll
        for (int mt = 0; mt < 2; mt++) {
#pragma unroll
            for (int nt = 0; nt < 8; nt++) {
                const int c0 = nt * 8 + tg * 2;
                const float bo0 = bo_sh[c0], bo1 = bo_sh[c0 + 1];
                const int r0 = rowbase + mt * 16 + g;
                {
                    const size_t base = ((size_t)(sbase + r0) * RDIM + r) * CE + c0;
                    const float2 av = *(const float2*)(add_to + base);
                    float2 ov;
                    ov.x = d[mt][nt][0] + bo0 + av.x;
                    ov.y = d[mt][nt][1] + bo1 + av.y;
                    *(float2*)(out + base) = ov;
                }
                {
                    const size_t base = ((size_t)(sbase + r0 + 8) * RDIM + r) * CE + c0;
                    const float2 av = *(const float2*)(add_to + base);
                    float2 ov;
                    ov.x = d[mt][nt][2] + bo0 + av.x;
                    ov.y = d[mt][nt][3] + bo1 + av.y;
                    *(float2*)(out + base) = ov;
                }
            }
        }
    }
}

// ============================================================================
extern "C" void kernel_launch(void* const* d_in, const int* in_sizes, int n_in,
                              void* d_out, int out_size) {
    const float* m      = (const float*)d_in[0];
    const float* mask   = (const float*)d_in[1];
    const float* Wq     = (const float*)d_in[2];
    const float* Wk     = (const float*)d_in[3];
    const float* Wv     = (const float*)d_in[4];
    const float* Wg     = (const float*)d_in[5];
    const float* bg     = (const float*)d_in[6];
    const float* Wo     = (const float*)d_in[7];
    const float* bo     = (const float*)d_in[8];
    const float* add_to = (const float*)d_in[9];
    float* out = (float*)d_out;

    cudaFuncSetAttribute(kv_kernel, cudaFuncAttributeMaxDynamicSharedMemorySize, KV_SMEM_BYTES);
    cudaFuncSetAttribute(gate_kernel, cudaFuncAttributeMaxDynamicSharedMemorySize, G_SMEM_BYTES);

    kv_kernel<<<KV_GRID, 128, KV_SMEM_BYTES>>>(m, mask, Wk, Wv);
    qk2_kernel<<<RDIM, 64>>>(Wq);
    attn3_kernel<<<dim3(NCH, RDIM), 256>>>(mask);
    combine2_kernel<<<RDIM, 64>>>();
    gate_kernel<<<G_GRID, 128, G_SMEM_BYTES>>>(m, Wg, bg, Wo, bo, add_to, out);
}

// round 12
// speedup vs baseline: 1.0755x; 1.0110x over previous
#include <cuda_runtime.h>
#include <cuda_bf16.h>
#include <cstdint>

typedef unsigned long long ull;
typedef unsigned int uint;

// ================= helpers =================
__device__ __forceinline__ void ffma2(ull& d, ull a, ull b) {
    asm("fma.rn.f32x2 %0, %1, %2, %0;" : "+l"(d) : "l"(a), "l"(b));
}
__device__ __forceinline__ ull pack2(float x, float y) {
    ull d; asm("mov.b64 %0, {%1, %2};" : "=l"(d) : "f"(x), "f"(y)); return d;
}
__device__ __forceinline__ float fast_sigmoid(float x) {
    float t;
    asm("tanh.approx.f32 %0, %1;" : "=f"(t) : "f"(x * 0.5f));
    return fmaf(t, 0.5f, 0.5f);
}
__device__ __forceinline__ uint bfpack(float x, float y) {
    __nv_bfloat16 bx = __float2bfloat16(x), by = __float2bfloat16(y);
    return (uint)__bfloat16_as_ushort(bx) | ((uint)__bfloat16_as_ushort(by) << 16);
}
__device__ __forceinline__ void split2(float x, float y, uint& hi, uint& lo) {
    __nv_bfloat16 hx = __float2bfloat16(x), hy = __float2bfloat16(y);
    hi = (uint)__bfloat16_as_ushort(hx) | ((uint)__bfloat16_as_ushort(hy) << 16);
    lo = bfpack(x - __bfloat162float(hx), y - __bfloat162float(hy));
}
__device__ __forceinline__ void mma_bf16(float* d, const uint* a, uint b0, uint b1) {
    asm volatile(
        "mma.sync.aligned.m16n8k16.row.col.f32.bf16.bf16.f32 "
        "{%0,%1,%2,%3}, {%4,%5,%6,%7}, {%8,%9}, {%0,%1,%2,%3};"
        : "+f"(d[0]), "+f"(d[1]), "+f"(d[2]), "+f"(d[3])
        : "r"(a[0]), "r"(a[1]), "r"(a[2]), "r"(a[3]), "r"(b0), "r"(b1));
}
__device__ __forceinline__ uint smem_u32(const void* p) {
    uint a;
    asm("{ .reg .u64 t; cvta.to.shared.u64 t, %1; cvt.u32.u64 %0, t; }" : "=r"(a) : "l"(p));
    return a;
}
__device__ __forceinline__ void cp_async16(uint saddr, const void* gptr) {
    asm volatile("cp.async.cg.shared.global [%0], [%1], 16;" :: "r"(saddr), "l"(gptr));
}
#define CP_COMMIT() asm volatile("cp.async.commit_group;" ::: "memory")
#define CP_WAIT0()  asm volatile("cp.async.wait_group 0;" ::: "memory")

// ================= constants =================
#define RDIM 384
#define SDIM 2048
#define CE   64
#define HC   64
#define QSCALE 0.35355339059327373f
#define BUFW  68
#define ASTW  36

// ================= scratch =================
__device__ float g_o[RDIM * HC];

// ============================================================================
// Fused attention kernel: one CTA per r, 256 threads (8 warps).
// Phase A: 16 m-tiles (128 rows) via cp.async double buffer; HMMA kv
//          projection into smem SoA kv_sh[c][s]; pooling partials in regs.
// Phase B: reduce pooling -> q -> qproj (in smem).
// Phase C: warp-per-head two-pass softmax from smem k/v -> g_o[r].
// ============================================================================
// smem float offsets
#define FA_KV    0                   // 16 x 2048 = 32768
#define FA_MB    32768               // 2 x 128 x 68 = 17408
#define FA_MASK  50176               // 2048
#define FA_W     52224               // 1152 words (wkv hi/lo)
#define FA_QRED  53376               // 8 x 64
#define FA_DRED  53888               // 8
#define FA_QPROJ 53896               // 64
#define FA_FLOATS 53968
#define FA_SMEM_BYTES (FA_FLOATS * 4)   // ~215.9 KB

__global__ void __launch_bounds__(256, 1)
fused_attn_kernel(const float* __restrict__ m, const float* __restrict__ mask,
                  const float* __restrict__ Wq, const float* __restrict__ Wk,
                  const float* __restrict__ Wv) {
    extern __shared__ __align__(16) float sfa[];
    float* kv_sh   = sfa + FA_KV;      // [c][s], c 0..7 = k, 8..15 = v
    float* mbuf[2] = { sfa + FA_MB, sfa + FA_MB + 128 * BUFW };
    float* mask_sh = sfa + FA_MASK;
    uint*  wkv_hi  = (uint*)(sfa + FA_W);
    uint*  wkv_lo  = wkv_hi + 16 * ASTW;
    float* qred    = sfa + FA_QRED;
    float* dred    = sfa + FA_DRED;
    float* qproj   = sfa + FA_QPROJ;

    const int r    = blockIdx.x;
    const int tid  = threadIdx.x;
    const int lane = tid & 31;
    const int warp = tid >> 5;
    const int g    = lane >> 2;
    const int tg   = lane & 3;
    const int rowbase = warp * 16;      // 8 warps x 16 rows = 128-row tile

    const uint mbuf_u32[2] = { smem_u32(mbuf[0]), smem_u32(mbuf[1]) };

    // stage Wkv hi/lo (rows 0..7 = Wk, 8..15 = Wv)
    for (int i = tid; i < 512; i += 256) {
        const int row = i >> 5, kp = i & 31;
        const float* W = (row < 8) ? (Wk + row * 64) : (Wv + (row - 8) * 64);
        float2 w = *(const float2*)(W + kp * 2);
        uint hi, lo; split2(w.x, w.y, hi, lo);
        wkv_hi[row * ASTW + kp] = hi;
        wkv_lo[row * ASTW + kp] = lo;
    }

    // prefetch tile 0
    {
#pragma unroll
        for (int i = 0; i < 8; i++) {
            const int idx = tid + 256 * i;
            const int row = idx >> 4;
            const int c4  = (idx & 15) * 4;
            cp_async16(mbuf_u32[0] + (uint)(row * BUFW + c4) * 4,
                       m + ((size_t)r * SDIM + row) * CE + c4);
        }
        CP_COMMIT();
    }

    ull qn = 0ull;          // masked sum, e = (2*lane, 2*lane+1)
    float qden = 0.0f;

    int cur = 0;
#pragma unroll 1
    for (int tile = 0; tile < 16; tile++, cur ^= 1) {
        const int sbase = tile * 128;

        CP_WAIT0();
        __syncthreads();

        if (tile + 1 < 16) {
            const int sbn = (tile + 1) * 128;
#pragma unroll
            for (int i = 0; i < 8; i++) {
                const int idx = tid + 256 * i;
                const int row = idx >> 4;
                const int c4  = (idx & 15) * 4;
                cp_async16(mbuf_u32[cur ^ 1] + (uint)(row * BUFW + c4) * 4,
                           m + ((size_t)r * SDIM + sbn + row) * CE + c4);
            }
            CP_COMMIT();
        }

        const float* buf = mbuf[cur];

        // ---- pooling partials + mask stash (warp covers its 16 rows) ----
        {
            const int sg = sbase + rowbase + (lane & 15);
            const float mskv = mask[(size_t)r * SDIM + sg];
            if (lane < 16) mask_sh[sg] = mskv;
#pragma unroll 8
            for (int i = 0; i < 16; i++) {
                const float msk = __shfl_sync(0xffffffffu, mskv, i);
                const ull mv = *(const ull*)&buf[(rowbase + i) * BUFW + 2 * lane];
                ffma2(qn, mv, pack2(msk, msk));
                qden += msk;
            }
        }

        // ---- kv GEMM: warp computes its 16 rows x 16 cols ----
        float d[2][4];
#pragma unroll
        for (int nt = 0; nt < 2; nt++)
#pragma unroll
            for (int q = 0; q < 4; q++) d[nt][q] = 0.0f;

#pragma unroll
        for (int kt = 0; kt < 4; kt++) {
            uint ah[4], al[4];
            {
                const int r0 = rowbase + g;
                const float2 f0 = *(const float2*)&buf[r0 * BUFW + 16 * kt + 2 * tg];
                const float2 f1 = *(const float2*)&buf[(r0 + 8) * BUFW + 16 * kt + 2 * tg];
                const float2 f2 = *(const float2*)&buf[r0 * BUFW + 16 * kt + 2 * tg + 8];
                const float2 f3 = *(const float2*)&buf[(r0 + 8) * BUFW + 16 * kt + 2 * tg + 8];
                split2(f0.x, f0.y, ah[0], al[0]);
                split2(f1.x, f1.y, ah[1], al[1]);
                split2(f2.x, f2.y, ah[2], al[2]);
                split2(f3.x, f3.y, ah[3], al[3]);
            }
#pragma unroll
            for (int p = 0; p < 3; p++) {
                const uint* wb = (p == 1) ? wkv_lo : wkv_hi;
                const uint* af = (p == 2) ? al : ah;
#pragma unroll
                for (int nt = 0; nt < 2; nt++) {
                    const uint b0 = wb[(nt * 8 + g) * ASTW + kt * 8 + tg];
                    const uint b1 = wb[(nt * 8 + g) * ASTW + kt * 8 + tg + 4];
                    mma_bf16(d[nt], af, b0, b1);
                }
            }
        }

        // ---- scatter to kv_sh [c][s] ----
#pragma unroll
        for (int nt = 0; nt < 2; nt++) {
            const int c0 = nt * 8 + 2 * tg;
            const int s0 = sbase + rowbase + g;
            kv_sh[c0 * SDIM + s0]           = d[nt][0];
            kv_sh[(c0 + 1) * SDIM + s0]     = d[nt][1];
            kv_sh[c0 * SDIM + s0 + 8]       = d[nt][2];
            kv_sh[(c0 + 1) * SDIM + s0 + 8] = d[nt][3];
        }
    }

    // ---- phase B: pooling reduce -> q -> qproj ----
    ((ull*)qred)[warp * 32 + lane] = qn;
    if (lane == 0) dred[warp] = qden;
    __syncthreads();

    if (tid < 64) {
        float qs = 0.0f;
#pragma unroll
        for (int w = 0; w < 8; w++) qs += qred[w * 64 + tid];
        float dt = 0.0f;
#pragma unroll
        for (int w = 0; w < 8; w++) dt += dred[w];
        const float qp = qs / (dt + 1e-10f);
        qred[tid] = qp;                 // reuse qred[0:64] as qpool
    }
    __syncthreads();
    if (tid < 64) {
        float acc = 0.0f;
        const float* wqr = Wq + tid * 64;
#pragma unroll
        for (int e = 0; e < 64; e++) acc = fmaf(qred[e], wqr[e], acc);
        qproj[tid] = acc * QSCALE;
    }
    __syncthreads();

    // ---- phase C: warp = head, two-pass softmax over s ----
    const int h = warp;
    float qh[8];
#pragma unroll
    for (int c = 0; c < 8; c++) qh[c] = qproj[h * 8 + c];

    float mx = -1e30f;
#pragma unroll 1
    for (int i = 0; i < 64; i++) {
        const int s = lane + 32 * i;
        float lg = (mask_sh[s] - 1.0f) * 1e9f;
#pragma unroll
        for (int c = 0; c < 8; c++) lg = fmaf(qh[c], kv_sh[c * SDIM + s], lg);
        mx = fmaxf(mx, lg);
    }
#pragma unroll
    for (int off = 16; off > 0; off >>= 1)
        mx = fmaxf(mx, __shfl_xor_sync(0xffffffffu, mx, off));

    float sum = 0.0f;
    float oacc[8];
#pragma unroll
    for (int c = 0; c < 8; c++) oacc[c] = 0.0f;
#pragma unroll 1
    for (int i = 0; i < 64; i++) {
        const int s = lane + 32 * i;
        float lg = (mask_sh[s] - 1.0f) * 1e9f;
#pragma unroll
        for (int c = 0; c < 8; c++) lg = fmaf(qh[c], kv_sh[c * SDIM + s], lg);
        const float e = __expf(lg - mx);
        sum += e;
#pragma unroll
        for (int c = 0; c < 8; c++)
            oacc[c] = fmaf(e, kv_sh[(8 + c) * SDIM + s], oacc[c]);
    }
#pragma unroll
    for (int off = 16; off > 0; off >>= 1) {
        sum += __shfl_xor_sync(0xffffffffu, sum, off);
#pragma unroll
        for (int c = 0; c < 8; c++)
            oacc[c] += __shfl_xor_sync(0xffffffffu, oacc[c], off);
    }
    if (lane == 0) {
        const float inv = 1.0f / sum;
#pragma unroll
        for (int c = 0; c < 8; c++)
            g_o[r * HC + h * 8 + c] = oacc[c] * inv;
    }
}

// ============================================================================
// Gate (exact round-8 structure: 128 thr, 2 CTA/SM, 128-row tiles, strided
// persistent tiles, m-only cp.async double buffer).
// ============================================================================
#define G_GRID 304
#define G_NT   (RDIM * (SDIM / 128))
#define G_BUF_FLOATS (128 * BUFW)
#define G_W_OFF  (2 * G_BUF_FLOATS)
#define G_SMEM_FLOATS (G_W_OFF + 4 * 64 * ASTW + 128)
#define G_SMEM_BYTES  (G_SMEM_FLOATS * 4)

__global__ void __launch_bounds__(128, 2)
gate_kernel(const float* __restrict__ m, const float* __restrict__ Wg,
            const float* __restrict__ bg, const float* __restrict__ Wo,
            const float* __restrict__ bo, const float* __restrict__ add_to,
            float* __restrict__ out) {
    extern __shared__ __align__(16) float sgf[];
    float* bufs[2] = { sgf, sgf + G_BUF_FLOATS };
    uint* wg_hi = (uint*)(sgf + G_W_OFF);
    uint* wg_lo = wg_hi + 64 * ASTW;
    uint* wo_hi = wg_lo + 64 * ASTW;
    uint* wo_lo = wo_hi + 64 * ASTW;
    float* bg_sh = (float*)(wo_lo + 64 * ASTW);
    float* bo_sh = bg_sh + 64;

    const int tid  = threadIdx.x;
    const int lane = tid & 31;
    const int warp = tid >> 5;
    const int g    = lane >> 2;
    const int tg   = lane & 3;
    const int rowbase = warp * 32;

    const uint buf_u32[2] = { smem_u32(bufs[0]), smem_u32(bufs[1]) };

    for (int i = tid; i < 2048; i += 128) {
        const int row = i >> 5, kp = i & 31;
        {
            float2 w = *(const float2*)(Wg + row * 64 + kp * 2);
            uint hi, lo; split2(w.x, w.y, hi, lo);
            wg_hi[row * ASTW + kp] = hi;
            wg_lo[row * ASTW + kp] = lo;
        }
        {
            float2 w = *(const float2*)(Wo + row * 64 + kp * 2);
            uint hi, lo; split2(w.x, w.y, hi, lo);
            wo_hi[row * ASTW + kp] = hi;
            wo_lo[row * ASTW + kp] = lo;
        }
    }
    if (tid < 64) {
        bg_sh[tid] = bg[tid];
        bo_sh[tid] = bo[tid];
    }

    int t0 = blockIdx.x;
    {
        const int r = t0 >> 4, sbase = (t0 & 15) * 128;
#pragma unroll
        for (int i = 0; i < 16; i++) {
            const int idx = tid + 128 * i;
            const int row = idx >> 4;
            const int c4  = (idx & 15) * 4;
            cp_async16(buf_u32[0] + (uint)(row * BUFW + c4) * 4,
                       m + ((size_t)r * SDIM + sbase + row) * CE + c4);
        }
        CP_COMMIT();
    }

    int cur = 0;
#pragma unroll 1
    for (int t = t0; t < G_NT; t += G_GRID, cur ^= 1) {
        const int r     = t >> 4;
        const int sbase = (t & 15) * 128;

        CP_WAIT0();
        __syncthreads();

        const int tn = t + G_GRID;
        if (tn < G_NT) {
            const int rn = tn >> 4, sbn = (tn & 15) * 128;
#pragma unroll
            for (int i = 0; i < 16; i++) {
                const int idx = tid + 128 * i;
                const int row = idx >> 4;
                const int c4  = (idx & 15) * 4;
                cp_async16(buf_u32[cur ^ 1] + (uint)(row * BUFW + c4) * 4,
                           m + ((size_t)rn * SDIM + sbn + row) * CE + c4);
            }
            CP_COMMIT();
        }

        const float* buf = bufs[cur];
        float d[2][8][4];

#pragma unroll
        for (int mt = 0; mt < 2; mt++)
#pragma unroll
            for (int nt = 0; nt < 8; nt++)
#pragma unroll
                for (int q = 0; q < 4; q++) d[mt][nt][q] = 0.0f;

#pragma unroll
        for (int kt = 0; kt < 4; kt++) {
            uint ah[2][4], al[2][4];
#pragma unroll
            for (int mt = 0; mt < 2; mt++) {
                const int r0 = rowbase + mt * 16 + g;
                const float2 f0 = *(const float2*)&buf[r0 * BUFW + 16 * kt + 2 * tg];
                const float2 f1 = *(const float2*)&buf[(r0 + 8) * BUFW + 16 * kt + 2 * tg];
                const float2 f2 = *(const float2*)&buf[r0 * BUFW + 16 * kt + 2 * tg + 8];
                const float2 f3 = *(const float2*)&buf[(r0 + 8) * BUFW + 16 * kt + 2 * tg + 8];
                split2(f0.x, f0.y, ah[mt][0], al[mt][0]);
                split2(f1.x, f1.y, ah[mt][1], al[mt][1]);
                split2(f2.x, f2.y, ah[mt][2], al[mt][2]);
                split2(f3.x, f3.y, ah[mt][3], al[mt][3]);
            }
#pragma unroll
            for (int p = 0; p < 3; p++) {
                const uint* wb = (p == 1) ? wg_lo : wg_hi;
                const uint (*af)[4] = (p == 2) ? al : ah;
#pragma unroll
                for (int nt = 0; nt < 8; nt++) {
                    const uint b0 = wb[(nt * 8 + g) * ASTW + kt * 8 + tg];
                    const uint b1 = wb[(nt * 8 + g) * ASTW + kt * 8 + tg + 4];
                    mma_bf16(d[0][nt], af[0], b0, b1);
                    mma_bf16(d[1][nt], af[1], b0, b1);
                }
            }
        }

        uint th[2][8][2], tl[2][8][2];
        {
            float ov0[8], ov1[8];
#pragma unroll
            for (int nt = 0; nt < 8; nt++) {
                const int c0 = nt * 8 + tg * 2;
                ov0[nt] = __ldg(&g_o[r * HC + c0]);
                ov1[nt] = __ldg(&g_o[r * HC + c0 + 1]);
            }
#pragma unroll
            for (int mt = 0; mt < 2; mt++) {
#pragma unroll
                for (int nt = 0; nt < 8; nt++) {
                    const int c0 = nt * 8 + tg * 2;
                    const float bg0 = bg_sh[c0], bg1 = bg_sh[c0 + 1];
                    const float t0 = fast_sigmoid(d[mt][nt][0] + bg0) * ov0[nt];
                    const float t1 = fast_sigmoid(d[mt][nt][1] + bg1) * ov1[nt];
                    const float t2 = fast_sigmoid(d[mt][nt][2] + bg0) * ov0[nt];
                    const float t3 = fast_sigmoid(d[mt][nt][3] + bg1) * ov1[nt];
                    split2(t0, t1, th[mt][nt][0], tl[mt][nt][0]);
                    split2(t2, t3, th[mt][nt][1], tl[mt][nt][1]);
                }
            }
        }

#pragma unroll
        for (int mt = 0; mt < 2; mt++)
#pragma unroll
            for (int nt = 0; nt < 8; nt++)
#pragma unroll
                for (int q = 0; q < 4; q++) d[mt][nt][q] = 0.0f;

#pragma unroll
        for (int p = 0; p < 3; p++) {
            const uint* wb = (p == 1) ? wo_lo : wo_hi;
#pragma unroll
            for (int kt = 0; kt < 4; kt++) {
                uint a[2][4];
#pragma unroll
                for (int mt = 0; mt < 2; mt++) {
                    if (p == 2) {
                        a[mt][0] = tl[mt][2 * kt][0];
                        a[mt][1] = tl[mt][2 * kt][1];
                        a[mt][2] = tl[mt][2 * kt + 1][0];
                        a[mt][3] = tl[mt][2 * kt + 1][1];
                    } else {
                        a[mt][0] = th[mt][2 * kt][0];
                        a[mt][1] = th[mt][2 * kt][1];
                        a[mt][2] = th[mt][2 * kt + 1][0];
                        a[mt][3] = th[mt][2 * kt + 1][1];
                    }
                }
#pragma unroll
                for (int nt = 0; nt < 8; nt++) {
                    const uint b0 = wb[(nt * 8 + g) * ASTW + kt * 8 + tg];
                    const uint b1 = wb[(nt * 8 + g) * ASTW + kt * 8 + tg + 4];
                    mma_bf16(d[0][nt], a[0], b0, b1);
                    mma_bf16(d[1][nt], a[1], b0, b1);
                }
            }
        }

#pragma unroll
        for (int mt = 0; mt < 2; mt++) {
#pragma unroll
            for (int nt = 0; nt < 8; nt++) {
                const int c0 = nt * 8 + tg * 2;
                const float bo0 = bo_sh[c0], bo1 = bo_sh[c0 + 1];
                const int r0 = rowbase + mt * 16 + g;
                {
                    const size_t base = ((size_t)(sbase + r0) * RDIM + r) * CE + c0;
                    const float2 av = *(const float2*)(add_to + base);
                    float2 ov;
                    ov.x = d[mt][nt][0] + bo0 + av.x;
                    ov.y = d[mt][nt][1] + bo1 + av.y;
                    *(float2*)(out + base) = ov;
                }
                {
                    const size_t base = ((size_t)(sbase + r0 + 8) * RDIM + r) * CE + c0;
                    const float2 av = *(const float2*)(add_to + base);
                    float2 ov;
                    ov.x = d[mt][nt][2] + bo0 + av.x;
                    ov.y = d[mt][nt][3] + bo1 + av.y;
                    *(float2*)(out + base) = ov;
                }
            }
        }
    }
}

// ============================================================================
extern "C" void kernel_launch(void* const* d_in, const int* in_sizes, int n_in,
                              void* d_out, int out_size) {
    const float* m      = (const float*)d_in[0];
    const float* mask   = (const float*)d_in[1];
    const float* Wq     = (const float*)d_in[2];
    const float* Wk     = (const float*)d_in[3];
    const float* Wv     = (const float*)d_in[4];
    const float* Wg     = (const float*)d_in[5];
    const float* bg     = (const float*)d_in[6];
    const float* Wo     = (const float*)d_in[7];
    const float* bo     = (const float*)d_in[8];
    const float* add_to = (const float*)d_in[9];
    float* out = (float*)d_out;

    cudaFuncSetAttribute(fused_attn_kernel, cudaFuncAttributeMaxDynamicSharedMemorySize,
                         FA_SMEM_BYTES);
    cudaFuncSetAttribute(gate_kernel, cudaFuncAttributeMaxDynamicSharedMemorySize,
                         G_SMEM_BYTES);

    fused_attn_kernel<<<RDIM, 256, FA_SMEM_BYTES>>>(m, mask, Wq, Wk, Wv);
    gate_kernel<<<G_GRID, 128, G_SMEM_BYTES>>>(m, Wg, bg, Wo, bo, add_to, out);
}